// round 2
// baseline (speedup 1.0000x reference)
#include <cuda_runtime.h>
#include <cuda_bf16.h>
#include <math.h>

// Problem constants
#define NN     20000
#define EE     320000
#define RNA    2000
#define PROT   100
#define EMB    256
#define HID    128
#define NHEAD  4
#define HD     512            // HID * NHEAD
#define INF    2100           // RNA + PROT
#define NEG_SLOPE 0.2f

// ---------------------------------------------------------------------------
// Scratch (device globals; no dynamic allocation allowed)
// ---------------------------------------------------------------------------
__device__ __align__(16) float g_h0[(size_t)NN * HD];
__device__ __align__(16) float g_h1[(size_t)NN * HD];
__device__ __align__(16) float g_xs[(size_t)NN * HD];
__device__ __align__(16) float g_xd[(size_t)NN * HD];
__device__ __align__(16) float g_lin[(size_t)NN * HD];
__device__ __align__(16) float g_asrc[(size_t)NN * NHEAD];
__device__ __align__(16) float g_adst[(size_t)NN * NHEAD];
__device__ int g_deg[NN];
__device__ int g_cursor[NN];
__device__ int g_rowptr[NN + 1];
__device__ int g_csr[EE];

// ---------------------------------------------------------------------------
// Generic fp32 SGEMM: C[M,N] = A[M,K](lda) @ B[K,N](ldb) (+bias1 +bias2)(+relu)
// 128x128x16 tiles, 8x8 per thread, 256 threads.
// ---------------------------------------------------------------------------
#define TM 128
#define TN 128
#define TK 16

__global__ void __launch_bounds__(256)
sgemm_kernel(const float* __restrict__ A, int lda,
             const float* __restrict__ B, int ldb,
             float* __restrict__ C, int ldc,
             int M, int N, int K,
             const float* __restrict__ bias1,
             const float* __restrict__ bias2,
             int do_relu)
{
    __shared__ float As[TK][TM + 4];
    __shared__ float Bs[TK][TN];

    const int tid = threadIdx.x;
    const int tx = tid & 15;       // 0..15  -> col group
    const int ty = tid >> 4;       // 0..15  -> row group
    const int row0 = blockIdx.y * TM;
    const int col0 = blockIdx.x * TN;

    float acc[8][8];
#pragma unroll
    for (int i = 0; i < 8; i++)
#pragma unroll
        for (int j = 0; j < 8; j++) acc[i][j] = 0.f;

    for (int k0 = 0; k0 < K; k0 += TK) {
        // Load A tile (TM x TK): idx -> k = idx%16, m = idx/16 (coalesced-ish rows)
#pragma unroll
        for (int i = 0; i < 8; i++) {
            int idx = tid + i * 256;
            int k = idx & 15;
            int m = idx >> 4;
            int gr = row0 + m, gk = k0 + k;
            float v = 0.f;
            if (gr < M && gk < K) v = A[(size_t)gr * lda + gk];
            As[k][m] = v;
        }
        // Load B tile (TK x TN): idx -> n = idx%128, k = idx/128 (coalesced)
#pragma unroll
        for (int i = 0; i < 8; i++) {
            int idx = tid + i * 256;
            int n = idx & 127;
            int k = idx >> 7;
            int gk = k0 + k, gc = col0 + n;
            float v = 0.f;
            if (gk < K && gc < N) v = B[(size_t)gk * ldb + gc];
            Bs[k][n] = v;
        }
        __syncthreads();

#pragma unroll
        for (int k = 0; k < TK; k++) {
            float a[8], b[8];
#pragma unroll
            for (int i = 0; i < 8; i++) a[i] = As[k][ty * 8 + i];
#pragma unroll
            for (int j = 0; j < 8; j++) b[j] = Bs[k][tx * 8 + j];
#pragma unroll
            for (int i = 0; i < 8; i++)
#pragma unroll
                for (int j = 0; j < 8; j++)
                    acc[i][j] = fmaf(a[i], b[j], acc[i][j]);
        }
        __syncthreads();
    }

#pragma unroll
    for (int i = 0; i < 8; i++) {
        int r = row0 + ty * 8 + i;
        if (r >= M) continue;
#pragma unroll
        for (int j = 0; j < 8; j++) {
            int c = col0 + tx * 8 + j;
            if (c >= N) continue;
            float v = acc[i][j];
            if (bias1) v += bias1[c];
            if (bias2) v += bias2[c];
            if (do_relu) v = fmaxf(v, 0.f);
            C[(size_t)r * ldc + c] = v;
        }
    }
}

// ---------------------------------------------------------------------------
// CSR build
// ---------------------------------------------------------------------------
__global__ void zero_int_kernel(int* p, int n)
{
    int i = blockIdx.x * blockDim.x + threadIdx.x;
    if (i < n) p[i] = 0;
}

__global__ void count_kernel(const int* __restrict__ dst, int* __restrict__ deg, int e)
{
    int i = blockIdx.x * blockDim.x + threadIdx.x;
    if (i < e) atomicAdd(&deg[dst[i]], 1);
}

// single-block exclusive scan over n ints (n up to a few 100k; tiles of 1024)
__global__ void scan_kernel(const int* __restrict__ deg, int* __restrict__ rowptr, int n)
{
    __shared__ int sh[1024];
    __shared__ int carry;
    int tid = threadIdx.x;
    if (tid == 0) carry = 0;
    __syncthreads();
    for (int base = 0; base < n; base += 1024) {
        int v = (base + tid < n) ? deg[base + tid] : 0;
        sh[tid] = v;
        __syncthreads();
        for (int off = 1; off < 1024; off <<= 1) {
            int t = (tid >= off) ? sh[tid - off] : 0;
            __syncthreads();
            sh[tid] += t;
            __syncthreads();
        }
        if (base + tid < n) rowptr[base + tid] = carry + sh[tid] - v;  // exclusive
        __syncthreads();
        if (tid == 1023) carry += sh[1023];
        __syncthreads();
    }
    if (tid == 0) rowptr[n] = carry;
}

__global__ void scatter_kernel(const int* __restrict__ src, const int* __restrict__ dst,
                               const int* __restrict__ rowptr, int* __restrict__ cursor,
                               int* __restrict__ csr, int e)
{
    int i = blockIdx.x * blockDim.x + threadIdx.x;
    if (i < e) {
        int d = dst[i];
        int pos = rowptr[d] + atomicAdd(&cursor[d], 1);
        csr[pos] = src[i];
    }
}

// ---------------------------------------------------------------------------
// Per-node attention coefficients: a_src[n,h] = <xs[n,h,:], a_s[h,:]>, same for dst
// grid = NN blocks, 128 threads (warp w handles head w)
// ---------------------------------------------------------------------------
__global__ void att_kernel(const float* __restrict__ xs, const float* __restrict__ xd,
                           const float* __restrict__ as, const float* __restrict__ ad,
                           float* __restrict__ a_src, float* __restrict__ a_dst)
{
    int node = blockIdx.x;
    int w = threadIdx.x >> 5;
    int lane = threadIdx.x & 31;
    const float* xsp = xs + (size_t)node * HD + w * HID;
    const float* xdp = xd + (size_t)node * HD + w * HID;
    const float* asp = as + w * HID;
    const float* adp = ad + w * HID;
    float s1 = 0.f, s2 = 0.f;
#pragma unroll
    for (int i = 0; i < 4; i++) {
        int d = lane + i * 32;
        s1 = fmaf(xsp[d], asp[d], s1);
        s2 = fmaf(xdp[d], adp[d], s2);
    }
#pragma unroll
    for (int o = 16; o > 0; o >>= 1) {
        s1 += __shfl_xor_sync(0xffffffffu, s1, o);
        s2 += __shfl_xor_sync(0xffffffffu, s2, o);
    }
    if (lane == 0) {
        a_src[node * NHEAD + w] = s1;
        a_dst[node * NHEAD + w] = s2;
    }
}

// ---------------------------------------------------------------------------
// GAT aggregation: one warp per destination node.
// Phase 1: per-head max of leaky_relu scores; phase 2: exp-sum; phase 3: gather.
// Epilogue: out = relu(agg + lin)  (lin already includes g_b + l_b)
// ---------------------------------------------------------------------------
__device__ __forceinline__ float leaky(float v) { return v > 0.f ? v : NEG_SLOPE * v; }

__global__ void __launch_bounds__(256)
agg_kernel(const int* __restrict__ rowptr, const int* __restrict__ csr,
           const float* __restrict__ a_src, const float* __restrict__ a_dst,
           const float* __restrict__ xs, const float* __restrict__ lin,
           float* __restrict__ out)
{
    int warp = (blockIdx.x * blockDim.x + threadIdx.x) >> 5;
    int lane = threadIdx.x & 31;
    if (warp >= NN) return;
    const int node = warp;
    const int beg = rowptr[node];
    const int end = rowptr[node + 1];

    const float ad0 = a_dst[node * 4 + 0];
    const float ad1 = a_dst[node * 4 + 1];
    const float ad2 = a_dst[node * 4 + 2];
    const float ad3 = a_dst[node * 4 + 3];

    // phase 1: max per head
    float m0 = -1e30f, m1 = -1e30f, m2 = -1e30f, m3 = -1e30f;
    for (int i = beg + lane; i < end; i += 32) {
        int s = csr[i];
        const float* ap = a_src + (size_t)s * 4;
        m0 = fmaxf(m0, leaky(ap[0] + ad0));
        m1 = fmaxf(m1, leaky(ap[1] + ad1));
        m2 = fmaxf(m2, leaky(ap[2] + ad2));
        m3 = fmaxf(m3, leaky(ap[3] + ad3));
    }
#pragma unroll
    for (int o = 16; o > 0; o >>= 1) {
        m0 = fmaxf(m0, __shfl_xor_sync(0xffffffffu, m0, o));
        m1 = fmaxf(m1, __shfl_xor_sync(0xffffffffu, m1, o));
        m2 = fmaxf(m2, __shfl_xor_sync(0xffffffffu, m2, o));
        m3 = fmaxf(m3, __shfl_xor_sync(0xffffffffu, m3, o));
    }

    // phase 2: exp-sum per head
    float s0 = 0.f, s1 = 0.f, s2 = 0.f, s3 = 0.f;
    for (int i = beg + lane; i < end; i += 32) {
        int s = csr[i];
        const float* ap = a_src + (size_t)s * 4;
        s0 += expf(leaky(ap[0] + ad0) - m0);
        s1 += expf(leaky(ap[1] + ad1) - m1);
        s2 += expf(leaky(ap[2] + ad2) - m2);
        s3 += expf(leaky(ap[3] + ad3) - m3);
    }
#pragma unroll
    for (int o = 16; o > 0; o >>= 1) {
        s0 += __shfl_xor_sync(0xffffffffu, s0, o);
        s1 += __shfl_xor_sync(0xffffffffu, s1, o);
        s2 += __shfl_xor_sync(0xffffffffu, s2, o);
        s3 += __shfl_xor_sync(0xffffffffu, s3, o);
    }

    // per-lane head selection: lane handles cols [lane*16, lane*16+16) -> head = lane/8
    const int myh = lane >> 3;
    const float m_my  = (myh < 2) ? (myh == 0 ? m0 : m1) : (myh == 2 ? m2 : m3);
    const float sum_my = (myh < 2) ? (myh == 0 ? s0 : s1) : (myh == 2 ? s2 : s3);
    const float ad_my = (myh < 2) ? (myh == 0 ? ad0 : ad1) : (myh == 2 ? ad2 : ad3);
    const float inv_my = 1.f / (sum_my + 1e-16f);

    float4 acc0 = make_float4(0.f, 0.f, 0.f, 0.f);
    float4 acc1 = acc0, acc2 = acc0, acc3 = acc0;

    // phase 3: weighted gather of source projections
    for (int i = beg; i < end; i++) {
        int s = csr[i];
        float v = leaky(a_src[(size_t)s * 4 + myh] + ad_my);
        float w = expf(v - m_my) * inv_my;
        const float4* xp = (const float4*)(xs + (size_t)s * HD + lane * 16);
        float4 x0 = xp[0], x1 = xp[1], x2 = xp[2], x3 = xp[3];
        acc0.x = fmaf(w, x0.x, acc0.x); acc0.y = fmaf(w, x0.y, acc0.y);
        acc0.z = fmaf(w, x0.z, acc0.z); acc0.w = fmaf(w, x0.w, acc0.w);
        acc1.x = fmaf(w, x1.x, acc1.x); acc1.y = fmaf(w, x1.y, acc1.y);
        acc1.z = fmaf(w, x1.z, acc1.z); acc1.w = fmaf(w, x1.w, acc1.w);
        acc2.x = fmaf(w, x2.x, acc2.x); acc2.y = fmaf(w, x2.y, acc2.y);
        acc2.z = fmaf(w, x2.z, acc2.z); acc2.w = fmaf(w, x2.w, acc2.w);
        acc3.x = fmaf(w, x3.x, acc3.x); acc3.y = fmaf(w, x3.y, acc3.y);
        acc3.z = fmaf(w, x3.z, acc3.z); acc3.w = fmaf(w, x3.w, acc3.w);
    }

    // epilogue: relu(agg + lin)
    const float4* lp = (const float4*)(lin + (size_t)node * HD + lane * 16);
    float4* op = (float4*)(out + (size_t)node * HD + lane * 16);
    float4 l0 = lp[0], l1 = lp[1], l2 = lp[2], l3 = lp[3];
    float4 r0, r1, r2, r3;
    r0.x = fmaxf(acc0.x + l0.x, 0.f); r0.y = fmaxf(acc0.y + l0.y, 0.f);
    r0.z = fmaxf(acc0.z + l0.z, 0.f); r0.w = fmaxf(acc0.w + l0.w, 0.f);
    r1.x = fmaxf(acc1.x + l1.x, 0.f); r1.y = fmaxf(acc1.y + l1.y, 0.f);
    r1.z = fmaxf(acc1.z + l1.z, 0.f); r1.w = fmaxf(acc1.w + l1.w, 0.f);
    r2.x = fmaxf(acc2.x + l2.x, 0.f); r2.y = fmaxf(acc2.y + l2.y, 0.f);
    r2.z = fmaxf(acc2.z + l2.z, 0.f); r2.w = fmaxf(acc2.w + l2.w, 0.f);
    r3.x = fmaxf(acc3.x + l3.x, 0.f); r3.y = fmaxf(acc3.y + l3.y, 0.f);
    r3.z = fmaxf(acc3.z + l3.z, 0.f); r3.w = fmaxf(acc3.w + l3.w, 0.f);
    op[0] = r0; op[1] = r1; op[2] = r2; op[3] = r3;
}

// ---------------------------------------------------------------------------
// Host side
// ---------------------------------------------------------------------------
static void gemm(const float* A, int lda, const float* B, int ldb,
                 float* C, int ldc, int M, int N, int K,
                 const float* b1, const float* b2, bool relu)
{
    dim3 grid((N + TN - 1) / TN, (M + TM - 1) / TM);
    sgemm_kernel<<<grid, 256>>>(A, lda, B, ldb, C, ldc, M, N, K, b1, b2, relu ? 1 : 0);
}

extern "C" void kernel_launch(void* const* d_in, const int* in_sizes, int n_in,
                              void* d_out, int out_size)
{
    const float* x      = (const float*)d_in[0];
    const int*   ei     = (const int*)d_in[1];
    const float* W_rna  = (const float*)d_in[2];
    const float* b_rna  = (const float*)d_in[3];
    const float* W_prot = (const float*)d_in[4];
    const float* b_prot = (const float*)d_in[5];
    const float* g1_ws  = (const float*)d_in[6];
    const float* g1_wd  = (const float*)d_in[7];
    const float* g1_as  = (const float*)d_in[8];
    const float* g1_ad  = (const float*)d_in[9];
    const float* g1_b   = (const float*)d_in[10];
    const float* l1_w   = (const float*)d_in[11];
    const float* l1_b   = (const float*)d_in[12];
    const float* g2_ws  = (const float*)d_in[13];
    const float* g2_wd  = (const float*)d_in[14];
    const float* g2_as  = (const float*)d_in[15];
    const float* g2_ad  = (const float*)d_in[16];
    const float* g2_b   = (const float*)d_in[17];
    const float* l2_w   = (const float*)d_in[18];
    const float* l2_b   = (const float*)d_in[19];
    const float* agg_w  = (const float*)d_in[20];
    const float* agg_b  = (const float*)d_in[21];
    const float* dr_w   = (const float*)d_in[22];
    const float* dr_b   = (const float*)d_in[23];
    const float* dp_w   = (const float*)d_in[24];
    const float* dp_b   = (const float*)d_in[25];
    const float* rr_w   = (const float*)d_in[26];
    const float* rr_b   = (const float*)d_in[27];
    const float* rp_w   = (const float*)d_in[28];
    const float* rp_b   = (const float*)d_in[29];

    float* out = (float*)d_out;
    float* out_rna  = out;                                   // [N, RNA]
    float* out_prot = out + (size_t)NN * RNA;                // [N, PROT]
    float* out_emb  = out + (size_t)NN * (RNA + PROT);       // [N, HID]

    float *h0, *h1, *xs, *xd, *lin, *asrc, *adst;
    int *deg, *cur, *rowptr, *csr;
    cudaGetSymbolAddress((void**)&h0,   g_h0);
    cudaGetSymbolAddress((void**)&h1,   g_h1);
    cudaGetSymbolAddress((void**)&xs,   g_xs);
    cudaGetSymbolAddress((void**)&xd,   g_xd);
    cudaGetSymbolAddress((void**)&lin,  g_lin);
    cudaGetSymbolAddress((void**)&asrc, g_asrc);
    cudaGetSymbolAddress((void**)&adst, g_adst);
    cudaGetSymbolAddress((void**)&deg,    g_deg);
    cudaGetSymbolAddress((void**)&cur,    g_cursor);
    cudaGetSymbolAddress((void**)&rowptr, g_rowptr);
    cudaGetSymbolAddress((void**)&csr,    g_csr);

    const int* e_src = ei;
    const int* e_dst = ei + EE;

    // ---- CSR build (edges grouped by destination) ----
    int nbN = (NN + 255) / 256;
    int nbE = (EE + 255) / 256;
    zero_int_kernel<<<nbN, 256>>>(deg, NN);
    zero_int_kernel<<<nbN, 256>>>(cur, NN);
    count_kernel<<<nbE, 256>>>(e_dst, deg, EE);
    scan_kernel<<<1, 1024>>>(deg, rowptr, NN);
    scatter_kernel<<<nbE, 256>>>(e_src, e_dst, rowptr, cur, csr, EE);

    // ---- input embeddings: h0 = [rna_e | prot_e] ----
    gemm(x,        INF, W_rna,  EMB, h0,        HD, NN, EMB, RNA,  b_rna,  nullptr, false);
    gemm(x + RNA,  INF, W_prot, EMB, h0 + EMB,  HD, NN, EMB, PROT, b_prot, nullptr, false);

    // ---- GAT layer 1 (in h0 -> out h1) ----
    gemm(h0, HD, g1_ws, HD, xs,  HD, NN, HD, HD, nullptr, nullptr, false);
    gemm(h0, HD, g1_wd, HD, xd,  HD, NN, HD, HD, nullptr, nullptr, false);
    gemm(h0, HD, l1_w,  HD, lin, HD, NN, HD, HD, l1_b,    g1_b,    false);
    att_kernel<<<NN, 128>>>(xs, xd, g1_as, g1_ad, asrc, adst);
    agg_kernel<<<(NN * 32 + 255) / 256, 256>>>(rowptr, csr, asrc, adst, xs, lin, h1);

    // ---- GAT layer 2 (in h1 -> out h0) ----
    gemm(h1, HD, g2_ws, HD, xs,  HD, NN, HD, HD, nullptr, nullptr, false);
    gemm(h1, HD, g2_wd, HD, xd,  HD, NN, HD, HD, nullptr, nullptr, false);
    gemm(h1, HD, l2_w,  HD, lin, HD, NN, HD, HD, l2_b,    g2_b,    false);
    att_kernel<<<NN, 128>>>(xs, xd, g2_as, g2_ad, asrc, adst);
    agg_kernel<<<(NN * 32 + 255) / 256, 256>>>(rowptr, csr, asrc, adst, xs, lin, h0);

    // ---- head ----
    // embedding = relu(h0 @ agg_w + agg_b) -> directly into output
    gemm(h0, HD, agg_w, HID, out_emb, HID, NN, HID, HD, agg_b, nullptr, true);
    // decoders (reuse xs/xd as scratch)
    gemm(out_emb, HID, dr_w, EMB, xs, EMB, NN, EMB, HID, dr_b, nullptr, false);
    gemm(out_emb, HID, dp_w, EMB, xd, EMB, NN, EMB, HID, dp_b, nullptr, false);
    // reconstructions
    gemm(xs, EMB, rr_w, RNA,  out_rna,  RNA,  NN, RNA,  EMB, rr_b, nullptr, false);
    gemm(xd, EMB, rp_w, PROT, out_prot, PROT, NN, PROT, EMB, rp_b, nullptr, false);
}

// round 4
// speedup vs baseline: 1.9835x; 1.9835x over previous
#include <cuda_runtime.h>
#include <cuda_bf16.h>
#include <math.h>
#include <stdint.h>

#define NN     20000
#define EE     320000
#define RNA    2000
#define PROT   100
#define EMB    256
#define HID    128
#define NHEAD  4
#define HD     512
#define INF    2100
#define NEG_SLOPE 0.2f

#define MPAD   20096
#define MTILES 157

#define STAGE_BYTES 65536            // Ah,Al,Bh,Bl x 16KB (128 rows x 128B)
#define GEMM_SMEM   (2 * STAGE_BYTES) // 128KB; epilogue fp32 reuses this region

// ---------------- device scratch (zero-init at load) ----------------
__device__ __align__(16) __nv_bfloat16 g_xr_h[(size_t)MPAD * 2048];
__device__ __align__(16) __nv_bfloat16 g_xr_l[(size_t)MPAD * 2048];
__device__ __align__(16) __nv_bfloat16 g_xp_h[(size_t)MPAD * 128];
__device__ __align__(16) __nv_bfloat16 g_xp_l[(size_t)MPAD * 128];
__device__ __align__(16) __nv_bfloat16 g_hh[(size_t)MPAD * 512];
__device__ __align__(16) __nv_bfloat16 g_hl[(size_t)MPAD * 512];
__device__ __align__(16) __nv_bfloat16 g_eh[(size_t)MPAD * 128];
__device__ __align__(16) __nv_bfloat16 g_el[(size_t)MPAD * 128];
__device__ __align__(16) __nv_bfloat16 g_rdh[(size_t)MPAD * 512];
__device__ __align__(16) __nv_bfloat16 g_rdl[(size_t)MPAD * 512];

__device__ __align__(16) float g_xs[(size_t)NN * HD];
__device__ __align__(16) float g_xd[(size_t)NN * HD];
__device__ __align__(16) float g_lin[(size_t)NN * HD];
__device__ __align__(16) float g_asrc[(size_t)NN * NHEAD];
__device__ __align__(16) float g_adst[(size_t)NN * NHEAD];

__device__ __align__(16) __nv_bfloat16 g_wr_h[256 * 2048],  g_wr_l[256 * 2048];
__device__ __align__(16) __nv_bfloat16 g_wp_h[256 * 128],   g_wp_l[256 * 128];
__device__ __align__(16) __nv_bfloat16 g_w1s_h[512 * 512],  g_w1s_l[512 * 512];
__device__ __align__(16) __nv_bfloat16 g_w1d_h[512 * 512],  g_w1d_l[512 * 512];
__device__ __align__(16) __nv_bfloat16 g_w1l_h[512 * 512],  g_w1l_l[512 * 512];
__device__ __align__(16) __nv_bfloat16 g_w2s_h[512 * 512],  g_w2s_l[512 * 512];
__device__ __align__(16) __nv_bfloat16 g_w2d_h[512 * 512],  g_w2d_l[512 * 512];
__device__ __align__(16) __nv_bfloat16 g_w2l_h[512 * 512],  g_w2l_l[512 * 512];
__device__ __align__(16) __nv_bfloat16 g_wagg_h[128 * 512], g_wagg_l[128 * 512];
__device__ __align__(16) __nv_bfloat16 g_wdr_h[256 * 128],  g_wdr_l[256 * 128];
__device__ __align__(16) __nv_bfloat16 g_wdp_h[256 * 128],  g_wdp_l[256 * 128];
__device__ __align__(16) __nv_bfloat16 g_wrr_h[2048 * 256], g_wrr_l[2048 * 256];
__device__ __align__(16) __nv_bfloat16 g_wrp_h[128 * 256],  g_wrp_l[128 * 256];

__device__ int g_deg[NN];
__device__ int g_cursor[NN];
__device__ int g_rowptr[NN + 1];
__device__ int g_csr[EE];

// ---------------- PTX helpers (all compute_103-baseline features) ----------
__device__ __forceinline__ uint32_t smem_u32(const void* p) {
    uint32_t a;
    asm("{ .reg .u64 t; cvta.to.shared.u64 t, %1; cvt.u32.u64 %0, t; }" : "=r"(a) : "l"(p));
    return a;
}
__device__ __forceinline__ void cp16(uint32_t dst, const void* src) {
    asm volatile("cp.async.cg.shared.global [%0], [%1], 16;" :: "r"(dst), "l"(src));
}
#define CP_COMMIT() asm volatile("cp.async.commit_group;" ::: "memory")
#define CP_WAIT(n)  asm volatile("cp.async.wait_group %0;" :: "n"(n) : "memory")

__device__ __forceinline__ uint32_t swz(uint32_t off) {
    return off ^ ((off >> 3) & 0x70);
}
__device__ __forceinline__ void ldm_x4(uint32_t addr, uint32_t r[4]) {
    asm volatile("ldmatrix.sync.aligned.m8n8.x4.shared.b16 {%0,%1,%2,%3}, [%4];"
                 : "=r"(r[0]), "=r"(r[1]), "=r"(r[2]), "=r"(r[3]) : "r"(addr));
}
__device__ __forceinline__ void mma_bf16(float c[4], const uint32_t a[4],
                                         uint32_t b0, uint32_t b1) {
    asm volatile(
        "mma.sync.aligned.m16n8k16.row.col.f32.bf16.bf16.f32 "
        "{%0,%1,%2,%3}, {%4,%5,%6,%7}, {%8,%9}, {%0,%1,%2,%3};"
        : "+f"(c[0]), "+f"(c[1]), "+f"(c[2]), "+f"(c[3])
        : "r"(a[0]), "r"(a[1]), "r"(a[2]), "r"(a[3]), "r"(b0), "r"(b1));
}

// ---------------- warp-MMA GEMM: C[MxN] = (Ah+Al) @ (Bh+Bl)^T ----------------
// A: [MPAD x lda] bf16 hi/lo (row-major, k contiguous)
// B: [Npad x ldb] bf16 hi/lo (pre-transposed, k contiguous)
// 128x128 tile/CTA, 8 warps of 64x32, K-chunks of 64, 3-pass hi/lo, fp32 accum.
__device__ __forceinline__ void load_chunk(
    uint32_t sb,
    const __nv_bfloat16* __restrict__ Ah, const __nv_bfloat16* __restrict__ Al, int lda,
    const __nv_bfloat16* __restrict__ Bh, const __nv_bfloat16* __restrict__ Bl, int ldb,
    int row0, int col0, int kOff, int tid)
{
#pragma unroll
    for (int j = 0; j < 16; j++) {
        int g = tid + j * 256;
        int sub = g >> 10;              // 0:Ah 1:Al 2:Bh 3:Bl
        int r = (g >> 3) & 127;
        int q = g & 7;
        const __nv_bfloat16* src;
        if (sub == 0)      src = Ah + (size_t)(row0 + r) * lda + kOff + q * 8;
        else if (sub == 1) src = Al + (size_t)(row0 + r) * lda + kOff + q * 8;
        else if (sub == 2) src = Bh + (size_t)(col0 + r) * ldb + kOff + q * 8;
        else               src = Bl + (size_t)(col0 + r) * ldb + kOff + q * 8;
        cp16(sb + (uint32_t)sub * 16384 + swz((uint32_t)(r * 128 + q * 16)), src);
    }
}

__global__ void __launch_bounds__(256, 1)
tc_gemm(const __nv_bfloat16* __restrict__ Ah, const __nv_bfloat16* __restrict__ Al, int lda,
        const __nv_bfloat16* __restrict__ Bh, const __nv_bfloat16* __restrict__ Bl, int ldb,
        float* __restrict__ C, int ldc,
        __nv_bfloat16* __restrict__ Chi, __nv_bfloat16* __restrict__ Clo, int ldhl,
        int M, int N, int nchunks,
        const float* __restrict__ bias1, const float* __restrict__ bias2, int relu)
{
    extern __shared__ char smem[];
    const uint32_t sm = smem_u32(smem);
    const int tid = threadIdx.x;
    const int wid = tid >> 5, lane = tid & 31;
    const int row0 = blockIdx.y * 128;
    const int col0 = blockIdx.x * 128;

    const int wm = wid & 1;             // 0..1 -> m offset 0/64
    const int wn = wid >> 1;            // 0..3 -> n offset 0/32/64/96

    // ldmatrix per-lane geometry
    const int li    = lane & 7;         // row within 8x8 matrix
    const int matm  = (lane >> 3) & 1;  // +8 row group
    const int khalf = lane >> 4;        // +16 bytes in k

    float acc[4][4][4];
#pragma unroll
    for (int a = 0; a < 4; a++)
#pragma unroll
        for (int b = 0; b < 4; b++)
#pragma unroll
            for (int c = 0; c < 4; c++) acc[a][b][c] = 0.f;

    // 2-stage pipeline
    load_chunk(sm, Ah, Al, lda, Bh, Bl, ldb, row0, col0, 0, tid);
    CP_COMMIT();

    for (int c = 0; c < nchunks; c++) {
        const uint32_t sb = sm + (uint32_t)(c & 1) * STAGE_BYTES;
        if (c + 1 < nchunks) {
            load_chunk(sm + (uint32_t)((c + 1) & 1) * STAGE_BYTES,
                       Ah, Al, lda, Bh, Bl, ldb, row0, col0, (c + 1) * 64, tid);
            CP_COMMIT();
            CP_WAIT(1);
        } else {
            CP_WAIT(0);
        }
        __syncthreads();

#pragma unroll
        for (int ks = 0; ks < 4; ks++) {
            const int kb = ks * 32 + khalf * 16;
            uint32_t ahf[4][4], alf[4][4], bhf[2][4], blf[2][4];
#pragma unroll
            for (int mi = 0; mi < 4; mi++) {
                const int r = wm * 64 + mi * 16 + matm * 8 + li;
                const uint32_t off = swz((uint32_t)(r * 128 + kb));
                ldm_x4(sb + off, ahf[mi]);
                ldm_x4(sb + 16384 + off, alf[mi]);
            }
#pragma unroll
            for (int nj = 0; nj < 2; nj++) {
                const int r = wn * 32 + nj * 16 + matm * 8 + li;
                const uint32_t off = swz((uint32_t)(r * 128 + kb));
                ldm_x4(sb + 32768 + off, bhf[nj]);
                ldm_x4(sb + 49152 + off, blf[nj]);
            }
#pragma unroll
            for (int mi = 0; mi < 4; mi++) {
#pragma unroll
                for (int ni = 0; ni < 4; ni++) {
                    const int nj = ni >> 1, sub = ni & 1;
                    mma_bf16(acc[mi][ni], ahf[mi], bhf[nj][sub], bhf[nj][sub + 2]);
                    mma_bf16(acc[mi][ni], ahf[mi], blf[nj][sub], blf[nj][sub + 2]);
                    mma_bf16(acc[mi][ni], alf[mi], bhf[nj][sub], bhf[nj][sub + 2]);
                }
            }
        }
        __syncthreads();
    }

    // epilogue: acc -> smem fp32 (stride 132) -> coalesced global
    float* eps = (float*)smem;
    const int grp = lane >> 2, qp = lane & 3;
#pragma unroll
    for (int mi = 0; mi < 4; mi++) {
#pragma unroll
        for (int ni = 0; ni < 4; ni++) {
            const int r = wm * 64 + mi * 16 + grp;
            const int col = wn * 32 + ni * 8 + qp * 2;
            eps[r * 132 + col]           = acc[mi][ni][0];
            eps[r * 132 + col + 1]       = acc[mi][ni][1];
            eps[(r + 8) * 132 + col]     = acc[mi][ni][2];
            eps[(r + 8) * 132 + col + 1] = acc[mi][ni][3];
        }
    }
    __syncthreads();

#pragma unroll
    for (int i = 0; i < 16; i++) {
        const int f = tid + i * 256;
        const int r = f >> 5, c4 = f & 31;
        const int grow = row0 + r;
        const int col = col0 + c4 * 4;
        if (grow >= M || col >= N) continue;
        float v[4];
#pragma unroll
        for (int j = 0; j < 4; j++) {
            v[j] = eps[r * 132 + c4 * 4 + j];
            const int cc = col + j;
            if (cc < N) {
                if (bias1) v[j] += bias1[cc];
                if (bias2) v[j] += bias2[cc];
                if (relu)  v[j] = fmaxf(v[j], 0.f);
            }
        }
        if (C) {
            if (col + 3 < N) {
                *(float4*)(C + (size_t)grow * ldc + col) = make_float4(v[0], v[1], v[2], v[3]);
            } else {
#pragma unroll
                for (int j = 0; j < 4; j++)
                    if (col + j < N) C[(size_t)grow * ldc + col + j] = v[j];
            }
        }
        if (Chi) {
#pragma unroll
            for (int j = 0; j < 4; j++) {
                if (col + j < N) {
                    __nv_bfloat16 h = __float2bfloat16(v[j]);
                    Chi[(size_t)grow * ldhl + col + j] = h;
                    Clo[(size_t)grow * ldhl + col + j] =
                        __float2bfloat16(v[j] - __bfloat162float(h));
                }
            }
        }
    }
}

// ---------------- conversions ----------------
__global__ void split_kernel(const float* __restrict__ A, int lds, int colOff,
                             int M, int K, int Kpad,
                             __nv_bfloat16* __restrict__ h, __nv_bfloat16* __restrict__ l,
                             long total)
{
    long idx = (long)blockIdx.x * blockDim.x + threadIdx.x;
    if (idx >= total) return;
    int r = (int)(idx / Kpad);
    int k = (int)(idx % Kpad);
    float v = 0.f;
    if (r < M && k < K) v = A[(size_t)r * lds + colOff + k];
    __nv_bfloat16 hi = __float2bfloat16(v);
    h[idx] = hi;
    l[idx] = __float2bfloat16(v - __bfloat162float(hi));
}

__global__ void tsplit_kernel(const float* __restrict__ W, int K, int N,
                              int Kpad, int Npad,
                              __nv_bfloat16* __restrict__ h, __nv_bfloat16* __restrict__ l)
{
    long idx = (long)blockIdx.x * blockDim.x + threadIdx.x;
    long total = (long)Npad * Kpad;
    if (idx >= total) return;
    int n = (int)(idx / Kpad);
    int k = (int)(idx % Kpad);
    float v = 0.f;
    if (n < N && k < K) v = W[(size_t)k * N + n];
    __nv_bfloat16 hi = __float2bfloat16(v);
    h[idx] = hi;
    l[idx] = __float2bfloat16(v - __bfloat162float(hi));
}

// ---------------- CSR build ----------------
__global__ void zero_int_kernel(int* p, int n)
{
    int i = blockIdx.x * blockDim.x + threadIdx.x;
    if (i < n) p[i] = 0;
}
__global__ void count_kernel(const int* __restrict__ dst, int* __restrict__ deg, int e)
{
    int i = blockIdx.x * blockDim.x + threadIdx.x;
    if (i < e) atomicAdd(&deg[dst[i]], 1);
}
__global__ void scan_kernel(const int* __restrict__ deg, int* __restrict__ rowptr, int n)
{
    __shared__ int wsum[32];
    __shared__ int carry_s;
    int tid = threadIdx.x, lane = tid & 31, wid = tid >> 5;
    if (tid == 0) carry_s = 0;
    __syncthreads();
    for (int base = 0; base < n; base += 1024) {
        int i = base + tid;
        int v = (i < n) ? deg[i] : 0;
        int s = v;
#pragma unroll
        for (int o = 1; o < 32; o <<= 1) {
            int t = __shfl_up_sync(0xffffffffu, s, o);
            if (lane >= o) s += t;
        }
        if (lane == 31) wsum[wid] = s;
        __syncthreads();
        if (wid == 0) {
            int ws = wsum[lane];
#pragma unroll
            for (int o = 1; o < 32; o <<= 1) {
                int t = __shfl_up_sync(0xffffffffu, ws, o);
                if (lane >= o) ws += t;
            }
            wsum[lane] = ws;
        }
        __syncthreads();
        int pre = (wid > 0) ? wsum[wid - 1] : 0;
        if (i < n) rowptr[i] = carry_s + pre + s - v;
        __syncthreads();
        if (tid == 0) carry_s += wsum[31];
        __syncthreads();
    }
    if (threadIdx.x == 0) rowptr[n] = carry_s;
}
__global__ void scatter_kernel(const int* __restrict__ src, const int* __restrict__ dst,
                               const int* __restrict__ rowptr, int* __restrict__ cursor,
                               int* __restrict__ csr, int e)
{
    int i = blockIdx.x * blockDim.x + threadIdx.x;
    if (i < e) {
        int d = dst[i];
        int pos = rowptr[d] + atomicAdd(&cursor[d], 1);
        csr[pos] = src[i];
    }
}

// ---------------- attention coefficients ----------------
__global__ void att_kernel(const float* __restrict__ xs, const float* __restrict__ xd,
                           const float* __restrict__ as, const float* __restrict__ ad,
                           float* __restrict__ a_src, float* __restrict__ a_dst)
{
    int node = blockIdx.x;
    int w = threadIdx.x >> 5;
    int lane = threadIdx.x & 31;
    const float* xsp = xs + (size_t)node * HD + w * HID;
    const float* xdp = xd + (size_t)node * HD + w * HID;
    const float* asp = as + w * HID;
    const float* adp = ad + w * HID;
    float s1 = 0.f, s2 = 0.f;
#pragma unroll
    for (int i = 0; i < 4; i++) {
        int d = lane + i * 32;
        s1 = fmaf(xsp[d], asp[d], s1);
        s2 = fmaf(xdp[d], adp[d], s2);
    }
#pragma unroll
    for (int o = 16; o > 0; o >>= 1) {
        s1 += __shfl_xor_sync(0xffffffffu, s1, o);
        s2 += __shfl_xor_sync(0xffffffffu, s2, o);
    }
    if (lane == 0) {
        a_src[node * NHEAD + w] = s1;
        a_dst[node * NHEAD + w] = s2;
    }
}

// ---------------- GAT aggregation (epilogue emits bf16 hi/lo) ----------------
__device__ __forceinline__ float leaky(float v) { return v > 0.f ? v : NEG_SLOPE * v; }

__global__ void __launch_bounds__(256)
agg_kernel(const int* __restrict__ rowptr, const int* __restrict__ csr,
           const float* __restrict__ a_src, const float* __restrict__ a_dst,
           const float* __restrict__ xs, const float* __restrict__ lin,
           __nv_bfloat16* __restrict__ out_h, __nv_bfloat16* __restrict__ out_l)
{
    int warp = (blockIdx.x * blockDim.x + threadIdx.x) >> 5;
    int lane = threadIdx.x & 31;
    if (warp >= NN) return;
    const int node = warp;
    const int beg = rowptr[node];
    const int end = rowptr[node + 1];

    const float ad0 = a_dst[node * 4 + 0];
    const float ad1 = a_dst[node * 4 + 1];
    const float ad2 = a_dst[node * 4 + 2];
    const float ad3 = a_dst[node * 4 + 3];

    float m0 = -1e30f, m1 = -1e30f, m2 = -1e30f, m3 = -1e30f;
    for (int i = beg + lane; i < end; i += 32) {
        int s = csr[i];
        const float* ap = a_src + (size_t)s * 4;
        m0 = fmaxf(m0, leaky(ap[0] + ad0));
        m1 = fmaxf(m1, leaky(ap[1] + ad1));
        m2 = fmaxf(m2, leaky(ap[2] + ad2));
        m3 = fmaxf(m3, leaky(ap[3] + ad3));
    }
#pragma unroll
    for (int o = 16; o > 0; o >>= 1) {
        m0 = fmaxf(m0, __shfl_xor_sync(0xffffffffu, m0, o));
        m1 = fmaxf(m1, __shfl_xor_sync(0xffffffffu, m1, o));
        m2 = fmaxf(m2, __shfl_xor_sync(0xffffffffu, m2, o));
        m3 = fmaxf(m3, __shfl_xor_sync(0xffffffffu, m3, o));
    }

    float s0 = 0.f, s1 = 0.f, s2 = 0.f, s3 = 0.f;
    for (int i = beg + lane; i < end; i += 32) {
        int s = csr[i];
        const float* ap = a_src + (size_t)s * 4;
        s0 += expf(leaky(ap[0] + ad0) - m0);
        s1 += expf(leaky(ap[1] + ad1) - m1);
        s2 += expf(leaky(ap[2] + ad2) - m2);
        s3 += expf(leaky(ap[3] + ad3) - m3);
    }
#pragma unroll
    for (int o = 16; o > 0; o >>= 1) {
        s0 += __shfl_xor_sync(0xffffffffu, s0, o);
        s1 += __shfl_xor_sync(0xffffffffu, s1, o);
        s2 += __shfl_xor_sync(0xffffffffu, s2, o);
        s3 += __shfl_xor_sync(0xffffffffu, s3, o);
    }

    const int myh = lane >> 3;
    const float m_my   = (myh < 2) ? (myh == 0 ? m0 : m1) : (myh == 2 ? m2 : m3);
    const float sum_my = (myh < 2) ? (myh == 0 ? s0 : s1) : (myh == 2 ? s2 : s3);
    const float ad_my  = (myh < 2) ? (myh == 0 ? ad0 : ad1) : (myh == 2 ? ad2 : ad3);
    const float inv_my = 1.f / (sum_my + 1e-16f);

    float4 acc0 = make_float4(0.f, 0.f, 0.f, 0.f);
    float4 acc1 = acc0, acc2 = acc0, acc3 = acc0;

    for (int i = beg; i < end; i++) {
        int s = csr[i];
        float v = leaky(a_src[(size_t)s * 4 + myh] + ad_my);
        float w = expf(v - m_my) * inv_my;
        const float4* xp = (const float4*)(xs + (size_t)s * HD + lane * 16);
        float4 x0 = xp[0], x1 = xp[1], x2 = xp[2], x3 = xp[3];
        acc0.x = fmaf(w, x0.x, acc0.x); acc0.y = fmaf(w, x0.y, acc0.y);
        acc0.z = fmaf(w, x0.z, acc0.z); acc0.w = fmaf(w, x0.w, acc0.w);
        acc1.x = fmaf(w, x1.x, acc1.x); acc1.y = fmaf(w, x1.y, acc1.y);
        acc1.z = fmaf(w, x1.z, acc1.z); acc1.w = fmaf(w, x1.w, acc1.w);
        acc2.x = fmaf(w, x2.x, acc2.x); acc2.y = fmaf(w, x2.y, acc2.y);
        acc2.z = fmaf(w, x2.z, acc2.z); acc2.w = fmaf(w, x2.w, acc2.w);
        acc3.x = fmaf(w, x3.x, acc3.x); acc3.y = fmaf(w, x3.y, acc3.y);
        acc3.z = fmaf(w, x3.z, acc3.z); acc3.w = fmaf(w, x3.w, acc3.w);
    }

    const float4* lp = (const float4*)(lin + (size_t)node * HD + lane * 16);
    float4 l0 = lp[0], l1 = lp[1], l2 = lp[2], l3 = lp[3];
    float r[16];
    r[0]  = fmaxf(acc0.x + l0.x, 0.f); r[1]  = fmaxf(acc0.y + l0.y, 0.f);
    r[2]  = fmaxf(acc0.z + l0.z, 0.f); r[3]  = fmaxf(acc0.w + l0.w, 0.f);
    r[4]  = fmaxf(acc1.x + l1.x, 0.f); r[5]  = fmaxf(acc1.y + l1.y, 0.f);
    r[6]  = fmaxf(acc1.z + l1.z, 0.f); r[7]  = fmaxf(acc1.w + l1.w, 0.f);
    r[8]  = fmaxf(acc2.x + l2.x, 0.f); r[9]  = fmaxf(acc2.y + l2.y, 0.f);
    r[10] = fmaxf(acc2.z + l2.z, 0.f); r[11] = fmaxf(acc2.w + l2.w, 0.f);
    r[12] = fmaxf(acc3.x + l3.x, 0.f); r[13] = fmaxf(acc3.y + l3.y, 0.f);
    r[14] = fmaxf(acc3.z + l3.z, 0.f); r[15] = fmaxf(acc3.w + l3.w, 0.f);

    size_t base = (size_t)node * HD + lane * 16;
#pragma unroll
    for (int j = 0; j < 16; j++) {
        __nv_bfloat16 h = __float2bfloat16(r[j]);
        out_h[base + j] = h;
        out_l[base + j] = __float2bfloat16(r[j] - __bfloat162float(h));
    }
}

// ---------------- host ----------------
static void tgemm(const __nv_bfloat16* Ah, const __nv_bfloat16* Al, int lda,
                  const __nv_bfloat16* Bh, const __nv_bfloat16* Bl, int ldb,
                  float* C, int ldc,
                  __nv_bfloat16* Chi, __nv_bfloat16* Clo, int ldhl,
                  int M, int N, int Npad, int nchunks,
                  const float* b1, const float* b2, int relu)
{
    dim3 grid(Npad / 128, MTILES);
    tc_gemm<<<grid, 256, GEMM_SMEM>>>(Ah, Al, lda, Bh, Bl, ldb, C, ldc,
                                      Chi, Clo, ldhl, M, N, nchunks, b1, b2, relu);
}

template <typename T>
static T* sym(T* s) { void* p = nullptr; cudaGetSymbolAddress(&p, (const void*)s); return (T*)p; }

extern "C" void kernel_launch(void* const* d_in, const int* in_sizes, int n_in,
                              void* d_out, int out_size)
{
    const float* x      = (const float*)d_in[0];
    const int*   ei     = (const int*)d_in[1];
    const float* W_rna  = (const float*)d_in[2];
    const float* b_rna  = (const float*)d_in[3];
    const float* W_prot = (const float*)d_in[4];
    const float* b_prot = (const float*)d_in[5];
    const float* g1_ws  = (const float*)d_in[6];
    const float* g1_wd  = (const float*)d_in[7];
    const float* g1_as  = (const float*)d_in[8];
    const float* g1_ad  = (const float*)d_in[9];
    const float* g1_b   = (const float*)d_in[10];
    const float* l1_w   = (const float*)d_in[11];
    const float* l1_b   = (const float*)d_in[12];
    const float* g2_ws  = (const float*)d_in[13];
    const float* g2_wd  = (const float*)d_in[14];
    const float* g2_as  = (const float*)d_in[15];
    const float* g2_ad  = (const float*)d_in[16];
    const float* g2_b   = (const float*)d_in[17];
    const float* l2_w   = (const float*)d_in[18];
    const float* l2_b   = (const float*)d_in[19];
    const float* agg_w  = (const float*)d_in[20];
    const float* agg_b  = (const float*)d_in[21];
    const float* dr_w   = (const float*)d_in[22];
    const float* dr_b   = (const float*)d_in[23];
    const float* dp_w   = (const float*)d_in[24];
    const float* dp_b   = (const float*)d_in[25];
    const float* rr_w   = (const float*)d_in[26];
    const float* rr_b   = (const float*)d_in[27];
    const float* rp_w   = (const float*)d_in[28];
    const float* rp_b   = (const float*)d_in[29];

    float* out = (float*)d_out;
    float* out_rna  = out;
    float* out_prot = out + (size_t)NN * RNA;
    float* out_emb  = out + (size_t)NN * (RNA + PROT);

    cudaFuncSetAttribute(tc_gemm, cudaFuncAttributeMaxDynamicSharedMemorySize, GEMM_SMEM);

    __nv_bfloat16 *xr_h = sym(g_xr_h), *xr_l = sym(g_xr_l);
    __nv_bfloat16 *xp_h = sym(g_xp_h), *xp_l = sym(g_xp_l);
    __nv_bfloat16 *hh = sym(g_hh), *hl = sym(g_hl);
    __nv_bfloat16 *eh = sym(g_eh), *el = sym(g_el);
    __nv_bfloat16 *rdh = sym(g_rdh), *rdl = sym(g_rdl);
    float *xs = sym(g_xs), *xd = sym(g_xd), *lin = sym(g_lin);
    float *asrc = sym(g_asrc), *adst = sym(g_adst);
    int *deg = sym(g_deg), *cur = sym(g_cursor), *rowptr = sym(g_rowptr), *csr = sym(g_csr);

    __nv_bfloat16 *wr_h = sym(g_wr_h), *wr_l = sym(g_wr_l);
    __nv_bfloat16 *wp_h = sym(g_wp_h), *wp_l = sym(g_wp_l);
    __nv_bfloat16 *w1s_h = sym(g_w1s_h), *w1s_l = sym(g_w1s_l);
    __nv_bfloat16 *w1d_h = sym(g_w1d_h), *w1d_l = sym(g_w1d_l);
    __nv_bfloat16 *w1l_h = sym(g_w1l_h), *w1l_l = sym(g_w1l_l);
    __nv_bfloat16 *w2s_h = sym(g_w2s_h), *w2s_l = sym(g_w2s_l);
    __nv_bfloat16 *w2d_h = sym(g_w2d_h), *w2d_l = sym(g_w2d_l);
    __nv_bfloat16 *w2l_h = sym(g_w2l_h), *w2l_l = sym(g_w2l_l);
    __nv_bfloat16 *wagg_h = sym(g_wagg_h), *wagg_l = sym(g_wagg_l);
    __nv_bfloat16 *wdr_h = sym(g_wdr_h), *wdr_l = sym(g_wdr_l);
    __nv_bfloat16 *wdp_h = sym(g_wdp_h), *wdp_l = sym(g_wdp_l);
    __nv_bfloat16 *wrr_h = sym(g_wrr_h), *wrr_l = sym(g_wrr_l);
    __nv_bfloat16 *wrp_h = sym(g_wrp_h), *wrp_l = sym(g_wrp_l);

    const int* e_src = ei;
    const int* e_dst = ei + EE;

    // CSR build
    int nbN = (NN + 255) / 256;
    int nbE = (EE + 255) / 256;
    zero_int_kernel<<<nbN, 256>>>(deg, NN);
    zero_int_kernel<<<nbN, 256>>>(cur, NN);
    count_kernel<<<nbE, 256>>>(e_dst, deg, EE);
    scan_kernel<<<1, 1024>>>(deg, rowptr, NN);
    scatter_kernel<<<nbE, 256>>>(e_src, e_dst, rowptr, cur, csr, EE);

    // input splits
    {
        long t1 = (long)MPAD * 2048;
        split_kernel<<<(unsigned)((t1 + 255) / 256), 256>>>(x, INF, 0, NN, RNA, 2048, xr_h, xr_l, t1);
        long t2 = (long)MPAD * 128;
        split_kernel<<<(unsigned)((t2 + 255) / 256), 256>>>(x, INF, RNA, NN, PROT, 128, xp_h, xp_l, t2);
    }

    // weight transposes+splits
    #define TSPLIT(W, K, N_, Kp, Np, H, L) \
        tsplit_kernel<<<(unsigned)(((long)(Np) * (Kp) + 255) / 256), 256>>>(W, K, N_, Kp, Np, H, L)
    TSPLIT(W_rna,  RNA,  EMB, 2048, 256, wr_h,  wr_l);
    TSPLIT(W_prot, PROT, EMB, 128,  256, wp_h,  wp_l);
    TSPLIT(g1_ws, HD, HD, 512, 512, w1s_h, w1s_l);
    TSPLIT(g1_wd, HD, HD, 512, 512, w1d_h, w1d_l);
    TSPLIT(l1_w,  HD, HD, 512, 512, w1l_h, w1l_l);
    TSPLIT(g2_ws, HD, HD, 512, 512, w2s_h, w2s_l);
    TSPLIT(g2_wd, HD, HD, 512, 512, w2d_h, w2d_l);
    TSPLIT(l2_w,  HD, HD, 512, 512, w2l_h, w2l_l);
    TSPLIT(agg_w, HD, HID, 512, 128, wagg_h, wagg_l);
    TSPLIT(dr_w, HID, EMB, 128, 256, wdr_h, wdr_l);
    TSPLIT(dp_w, HID, EMB, 128, 256, wdp_h, wdp_l);
    TSPLIT(rr_w, EMB, RNA, 256, 2048, wrr_h, wrr_l);
    TSPLIT(rp_w, EMB, PROT, 256, 128, wrp_h, wrp_l);

    // input embeddings -> hh/hl [N x 512] (cols 0-255 rna, 256-511 prot)
    tgemm(xr_h, xr_l, 2048, wr_h, wr_l, 2048, nullptr, 0, hh, hl, 512,
          NN, 256, 256, 32, b_rna, nullptr, 0);
    tgemm(xp_h, xp_l, 128, wp_h, wp_l, 128, nullptr, 0, hh + 256, hl + 256, 512,
          NN, 256, 256, 2, b_prot, nullptr, 0);

    // GAT layer 1
    tgemm(hh, hl, 512, w1s_h, w1s_l, 512, xs, 512, nullptr, nullptr, 0,
          NN, 512, 512, 8, nullptr, nullptr, 0);
    tgemm(hh, hl, 512, w1d_h, w1d_l, 512, xd, 512, nullptr, nullptr, 0,
          NN, 512, 512, 8, nullptr, nullptr, 0);
    tgemm(hh, hl, 512, w1l_h, w1l_l, 512, lin, 512, nullptr, nullptr, 0,
          NN, 512, 512, 8, l1_b, g1_b, 0);
    att_kernel<<<NN, 128>>>(xs, xd, g1_as, g1_ad, asrc, adst);
    agg_kernel<<<(NN * 32 + 255) / 256, 256>>>(rowptr, csr, asrc, adst, xs, lin, hh, hl);

    // GAT layer 2
    tgemm(hh, hl, 512, w2s_h, w2s_l, 512, xs, 512, nullptr, nullptr, 0,
          NN, 512, 512, 8, nullptr, nullptr, 0);
    tgemm(hh, hl, 512, w2d_h, w2d_l, 512, xd, 512, nullptr, nullptr, 0,
          NN, 512, 512, 8, nullptr, nullptr, 0);
    tgemm(hh, hl, 512, w2l_h, w2l_l, 512, lin, 512, nullptr, nullptr, 0,
          NN, 512, 512, 8, l2_b, g2_b, 0);
    att_kernel<<<NN, 128>>>(xs, xd, g2_as, g2_ad, asrc, adst);
    agg_kernel<<<(NN * 32 + 255) / 256, 256>>>(rowptr, csr, asrc, adst, xs, lin, hh, hl);

    // embedding = relu(h @ agg_w + agg_b): fp32 -> out_emb, hi/lo -> eh/el
    tgemm(hh, hl, 512, wagg_h, wagg_l, 512, out_emb, HID, eh, el, 128,
          NN, HID, 128, 8, agg_b, nullptr, 1);

    // decoders: rna_d -> rdh/rdl cols 0-255, prot_d -> cols 256-511
    tgemm(eh, el, 128, wdr_h, wdr_l, 128, nullptr, 0, rdh, rdl, 512,
          NN, 256, 256, 2, dr_b, nullptr, 0);
    tgemm(eh, el, 128, wdp_h, wdp_l, 128, nullptr, 0, rdh + 256, rdl + 256, 512,
          NN, 256, 256, 2, dp_b, nullptr, 0);

    // reconstructions
    tgemm(rdh, rdl, 512, wrr_h, wrr_l, 256, out_rna, RNA, nullptr, nullptr, 0,
          NN, RNA, 2048, 4, rr_b, nullptr, 0);
    tgemm(rdh + 256, rdl + 256, 512, wrp_h, wrp_l, 256, out_prot, PROT, nullptr, nullptr, 0,
          NN, PROT, 128, 4, rp_b, nullptr, 0);
}

// round 5
// speedup vs baseline: 2.0117x; 1.0142x over previous
#include <cuda_runtime.h>
#include <cuda_bf16.h>
#include <math.h>
#include <stdint.h>

#define NN     20000
#define EE     320000
#define RNA    2000
#define PROT   100
#define EMB    256
#define HID    128
#define NHEAD  4
#define HD     512
#define INF    2100
#define NEG_SLOPE 0.2f

#define MPAD   20096
#define MTILES 157

#define STAGES      3
#define STAGE_BYTES 65536                 // Ah,Al,Bh,Bl x 16KB
#define GEMM_SMEM   (STAGES * STAGE_BYTES)

// ---------------- device scratch (zero-init at load) ----------------
__device__ __align__(16) __nv_bfloat16 g_xr_h[(size_t)MPAD * 2048];
__device__ __align__(16) __nv_bfloat16 g_xr_l[(size_t)MPAD * 2048];
__device__ __align__(16) __nv_bfloat16 g_xp_h[(size_t)MPAD * 128];
__device__ __align__(16) __nv_bfloat16 g_xp_l[(size_t)MPAD * 128];
__device__ __align__(16) __nv_bfloat16 g_hh[(size_t)MPAD * 512];
__device__ __align__(16) __nv_bfloat16 g_hl[(size_t)MPAD * 512];
__device__ __align__(16) __nv_bfloat16 g_eh[(size_t)MPAD * 128];
__device__ __align__(16) __nv_bfloat16 g_el[(size_t)MPAD * 128];
__device__ __align__(16) __nv_bfloat16 g_rdh[(size_t)MPAD * 512];
__device__ __align__(16) __nv_bfloat16 g_rdl[(size_t)MPAD * 512];

__device__ __align__(16) float g_xslin[(size_t)MPAD * 1024];   // xs cols 0-511, lin cols 512-1023
__device__ __align__(16) float g_asrc[(size_t)NN * NHEAD];
__device__ __align__(16) float g_adst[(size_t)NN * NHEAD];
__device__ __align__(16) float g_wp1[8 * 512];                 // [j][k] layout
__device__ __align__(16) float g_wp2[8 * 512];
__device__ __align__(16) float g_bcat1[1024];
__device__ __align__(16) float g_bcat2[1024];
__device__ __align__(16) float g_bcatd[512];

__device__ __align__(16) __nv_bfloat16 g_wr_h[256 * 2048],   g_wr_l[256 * 2048];
__device__ __align__(16) __nv_bfloat16 g_wp_h[256 * 128],    g_wp_l[256 * 128];
__device__ __align__(16) __nv_bfloat16 g_wc1_h[1024 * 512],  g_wc1_l[1024 * 512];  // [w1s | l1_w]
__device__ __align__(16) __nv_bfloat16 g_wc2_h[1024 * 512],  g_wc2_l[1024 * 512];  // [w2s | l2_w]
__device__ __align__(16) __nv_bfloat16 g_wagg_h[128 * 512],  g_wagg_l[128 * 512];
__device__ __align__(16) __nv_bfloat16 g_wdc_h[512 * 128],   g_wdc_l[512 * 128];   // [dr_w | dp_w]
__device__ __align__(16) __nv_bfloat16 g_wrr_h[2048 * 256],  g_wrr_l[2048 * 256];
__device__ __align__(16) __nv_bfloat16 g_wrp_h[128 * 256],   g_wrp_l[128 * 256];

__device__ int g_deg[NN];
__device__ int g_cursor[NN];
__device__ int g_rowptr[NN + 1];
__device__ int g_csr[EE];

// ---------------- PTX helpers ----------------
__device__ __forceinline__ uint32_t smem_u32(const void* p) {
    uint32_t a;
    asm("{ .reg .u64 t; cvta.to.shared.u64 t, %1; cvt.u32.u64 %0, t; }" : "=r"(a) : "l"(p));
    return a;
}
__device__ __forceinline__ void cp16(uint32_t dst, const void* src) {
    asm volatile("cp.async.cg.shared.global [%0], [%1], 16;" :: "r"(dst), "l"(src));
}
#define CP_COMMIT() asm volatile("cp.async.commit_group;" ::: "memory")
#define CP_WAIT(n)  asm volatile("cp.async.wait_group %0;" :: "n"(n) : "memory")

__device__ __forceinline__ uint32_t swz(uint32_t off) {
    return off ^ ((off >> 3) & 0x70);
}
__device__ __forceinline__ void ldm_x4(uint32_t addr, uint32_t r[4]) {
    asm volatile("ldmatrix.sync.aligned.m8n8.x4.shared.b16 {%0,%1,%2,%3}, [%4];"
                 : "=r"(r[0]), "=r"(r[1]), "=r"(r[2]), "=r"(r[3]) : "r"(addr));
}
__device__ __forceinline__ void mma_bf16(float c[4], const uint32_t a[4],
                                         uint32_t b0, uint32_t b1) {
    asm volatile(
        "mma.sync.aligned.m16n8k16.row.col.f32.bf16.bf16.f32 "
        "{%0,%1,%2,%3}, {%4,%5,%6,%7}, {%8,%9}, {%0,%1,%2,%3};"
        : "+f"(c[0]), "+f"(c[1]), "+f"(c[2]), "+f"(c[3])
        : "r"(a[0]), "r"(a[1]), "r"(a[2]), "r"(a[3]), "r"(b0), "r"(b1));
}

// ---------------- warp-MMA GEMM (3-stage cp.async pipeline) ----------------
__device__ __forceinline__ void load_chunk(
    uint32_t sb,
    const __nv_bfloat16* __restrict__ Ah, const __nv_bfloat16* __restrict__ Al, int lda,
    const __nv_bfloat16* __restrict__ Bh, const __nv_bfloat16* __restrict__ Bl, int ldb,
    int row0, int col0, int kOff, int tid)
{
#pragma unroll
    for (int j = 0; j < 16; j++) {
        int g = tid + j * 256;
        int sub = g >> 10;              // 0:Ah 1:Al 2:Bh 3:Bl
        int r = (g >> 3) & 127;
        int q = g & 7;
        const __nv_bfloat16* src;
        if (sub == 0)      src = Ah + (size_t)(row0 + r) * lda + kOff + q * 8;
        else if (sub == 1) src = Al + (size_t)(row0 + r) * lda + kOff + q * 8;
        else if (sub == 2) src = Bh + (size_t)(col0 + r) * ldb + kOff + q * 8;
        else               src = Bl + (size_t)(col0 + r) * ldb + kOff + q * 8;
        cp16(sb + (uint32_t)sub * 16384 + swz((uint32_t)(r * 128 + q * 16)), src);
    }
}

__global__ void __launch_bounds__(256, 1)
tc_gemm(const __nv_bfloat16* __restrict__ Ah, const __nv_bfloat16* __restrict__ Al, int lda,
        const __nv_bfloat16* __restrict__ Bh, const __nv_bfloat16* __restrict__ Bl, int ldb,
        float* __restrict__ C, int ldc,
        __nv_bfloat16* __restrict__ Chi, __nv_bfloat16* __restrict__ Clo, int ldhl,
        int M, int N, int nchunks,
        const float* __restrict__ bias1, const float* __restrict__ bias2, int relu)
{
    extern __shared__ char smem[];
    const uint32_t sm = smem_u32(smem);
    const int tid = threadIdx.x;
    const int wid = tid >> 5, lane = tid & 31;
    const int row0 = blockIdx.y * 128;
    const int col0 = blockIdx.x * 128;

    const int wm = wid & 1;
    const int wn = wid >> 1;
    const int li    = lane & 7;
    const int matm  = (lane >> 3) & 1;
    const int khalf = lane >> 4;

    float acc[4][4][4];
#pragma unroll
    for (int a = 0; a < 4; a++)
#pragma unroll
        for (int b = 0; b < 4; b++)
#pragma unroll
            for (int c = 0; c < 4; c++) acc[a][b][c] = 0.f;

    // prologue: fill up to STAGES-1 stages
    load_chunk(sm, Ah, Al, lda, Bh, Bl, ldb, row0, col0, 0, tid);
    CP_COMMIT();
    if (nchunks > 1) {
        load_chunk(sm + STAGE_BYTES, Ah, Al, lda, Bh, Bl, ldb, row0, col0, 64, tid);
        CP_COMMIT();
    }

    for (int c = 0; c < nchunks; c++) {
        const uint32_t sb = sm + (uint32_t)(c % STAGES) * STAGE_BYTES;
        if (c + 2 < nchunks) {
            load_chunk(sm + (uint32_t)((c + 2) % STAGES) * STAGE_BYTES,
                       Ah, Al, lda, Bh, Bl, ldb, row0, col0, (c + 2) * 64, tid);
            CP_COMMIT();
            CP_WAIT(2);
        } else if (c + 1 < nchunks) {
            CP_WAIT(1);
        } else {
            CP_WAIT(0);
        }
        __syncthreads();

#pragma unroll
        for (int ks = 0; ks < 4; ks++) {
            const int kb = ks * 32 + khalf * 16;
            uint32_t ahf[4][4], alf[4][4], bhf[2][4], blf[2][4];
#pragma unroll
            for (int mi = 0; mi < 4; mi++) {
                const int r = wm * 64 + mi * 16 + matm * 8 + li;
                const uint32_t off = swz((uint32_t)(r * 128 + kb));
                ldm_x4(sb + off, ahf[mi]);
                ldm_x4(sb + 16384 + off, alf[mi]);
            }
#pragma unroll
            for (int nj = 0; nj < 2; nj++) {
                const int r = wn * 32 + nj * 16 + matm * 8 + li;
                const uint32_t off = swz((uint32_t)(r * 128 + kb));
                ldm_x4(sb + 32768 + off, bhf[nj]);
                ldm_x4(sb + 49152 + off, blf[nj]);
            }
#pragma unroll
            for (int mi = 0; mi < 4; mi++) {
#pragma unroll
                for (int ni = 0; ni < 4; ni++) {
                    const int nj = ni >> 1, sub = ni & 1;
                    mma_bf16(acc[mi][ni], ahf[mi], bhf[nj][sub], bhf[nj][sub + 2]);
                    mma_bf16(acc[mi][ni], ahf[mi], blf[nj][sub], blf[nj][sub + 2]);
                    mma_bf16(acc[mi][ni], alf[mi], bhf[nj][sub], bhf[nj][sub + 2]);
                }
            }
        }
        __syncthreads();
    }

    // epilogue: acc -> smem fp32 (stride 132) -> coalesced global
    float* eps = (float*)smem;
    const int grp = lane >> 2, qp = lane & 3;
#pragma unroll
    for (int mi = 0; mi < 4; mi++) {
#pragma unroll
        for (int ni = 0; ni < 4; ni++) {
            const int r = wm * 64 + mi * 16 + grp;
            const int col = wn * 32 + ni * 8 + qp * 2;
            eps[r * 132 + col]           = acc[mi][ni][0];
            eps[r * 132 + col + 1]       = acc[mi][ni][1];
            eps[(r + 8) * 132 + col]     = acc[mi][ni][2];
            eps[(r + 8) * 132 + col + 1] = acc[mi][ni][3];
        }
    }
    __syncthreads();

#pragma unroll
    for (int i = 0; i < 16; i++) {
        const int f = tid + i * 256;
        const int r = f >> 5, c4 = f & 31;
        const int grow = row0 + r;
        const int col = col0 + c4 * 4;
        if (grow >= M || col >= N) continue;
        float v[4];
#pragma unroll
        for (int j = 0; j < 4; j++) {
            v[j] = eps[r * 132 + c4 * 4 + j];
            const int cc = col + j;
            if (cc < N) {
                if (bias1) v[j] += bias1[cc];
                if (bias2) v[j] += bias2[cc];
                if (relu)  v[j] = fmaxf(v[j], 0.f);
            }
        }
        if (C) {
            if (col + 3 < N) {
                *(float4*)(C + (size_t)grow * ldc + col) = make_float4(v[0], v[1], v[2], v[3]);
            } else {
#pragma unroll
                for (int j = 0; j < 4; j++)
                    if (col + j < N) C[(size_t)grow * ldc + col + j] = v[j];
            }
        }
        if (Chi) {
#pragma unroll
            for (int j = 0; j < 4; j++) {
                if (col + j < N) {
                    __nv_bfloat16 h = __float2bfloat16(v[j]);
                    Chi[(size_t)grow * ldhl + col + j] = h;
                    Clo[(size_t)grow * ldhl + col + j] =
                        __float2bfloat16(v[j] - __bfloat162float(h));
                }
            }
        }
    }
}

// ---------------- conversions ----------------
__global__ void split_kernel(const float* __restrict__ A, int lds, int colOff,
                             int M, int K, int Kpad,
                             __nv_bfloat16* __restrict__ h, __nv_bfloat16* __restrict__ l,
                             long total)
{
    long idx = (long)blockIdx.x * blockDim.x + threadIdx.x;
    if (idx >= total) return;
    int r = (int)(idx / Kpad);
    int k = (int)(idx % Kpad);
    float v = 0.f;
    if (r < M && k < K) v = A[(size_t)r * lds + colOff + k];
    __nv_bfloat16 hi = __float2bfloat16(v);
    h[idx] = hi;
    l[idx] = __float2bfloat16(v - __bfloat162float(hi));
}

__global__ void tsplit_kernel(const float* __restrict__ W, int K, int N,
                              int Kpad, int Npad,
                              __nv_bfloat16* __restrict__ h, __nv_bfloat16* __restrict__ l)
{
    long idx = (long)blockIdx.x * blockDim.x + threadIdx.x;
    long total = (long)Npad * Kpad;
    if (idx >= total) return;
    int n = (int)(idx / Kpad);
    int k = (int)(idx % Kpad);
    float v = 0.f;
    if (n < N && k < K) v = W[(size_t)k * N + n];
    __nv_bfloat16 hi = __float2bfloat16(v);
    h[idx] = hi;
    l[idx] = __float2bfloat16(v - __bfloat162float(hi));
}

// attention projection vectors: wp[j][k] (j: 0-3 src heads, 4-7 dst heads)
__global__ void wproj_kernel(const float* __restrict__ ws, const float* __restrict__ wd,
                             const float* __restrict__ as_, const float* __restrict__ ad_,
                             float* __restrict__ wp)
{
    int k = blockIdx.x * blockDim.x + threadIdx.x;
    if (k >= 512) return;
#pragma unroll
    for (int h = 0; h < 4; h++) {
        float s1 = 0.f, s2 = 0.f;
        for (int d = 0; d < 128; d++) {
            s1 = fmaf(ws[(size_t)k * 512 + h * 128 + d], as_[h * 128 + d], s1);
            s2 = fmaf(wd[(size_t)k * 512 + h * 128 + d], ad_[h * 128 + d], s2);
        }
        wp[h * 512 + k] = s1;
        wp[(4 + h) * 512 + k] = s2;
    }
}

// bias concat: layer (1024: zeros | l_b+g_b)
__global__ void biascat_layer_kernel(const float* __restrict__ lb, const float* __restrict__ gb,
                                     float* __restrict__ out)
{
    int i = blockIdx.x * blockDim.x + threadIdx.x;
    if (i < 512) out[i] = 0.f;
    else if (i < 1024) out[i] = lb[i - 512] + gb[i - 512];
}
// bias concat: decoder (512: dr_b | dp_b)
__global__ void biascat_dec_kernel(const float* __restrict__ a, const float* __restrict__ b,
                                   float* __restrict__ out)
{
    int i = blockIdx.x * blockDim.x + threadIdx.x;
    if (i < 256) out[i] = a[i];
    else if (i < 512) out[i] = b[i - 256];
}

// attention coefficients: asrc/adst[n,h] = (hh+hl)[n,:] . wp[j,:]
__global__ void __launch_bounds__(256)
coef_kernel(const __nv_bfloat16* __restrict__ hh, const __nv_bfloat16* __restrict__ hl,
            const float* __restrict__ wp,
            float* __restrict__ asrc, float* __restrict__ adst)
{
    __shared__ float swp[8 * 512];
    for (int i = threadIdx.x; i < 8 * 512; i += blockDim.x) swp[i] = wp[i];
    __syncthreads();
    int warp = (blockIdx.x * blockDim.x + threadIdx.x) >> 5;
    int lane = threadIdx.x & 31;
    if (warp >= NN) return;
    float acc[8] = {0.f, 0.f, 0.f, 0.f, 0.f, 0.f, 0.f, 0.f};
    const size_t base = (size_t)warp * 512;
#pragma unroll
    for (int i = 0; i < 16; i++) {
        int k = lane + i * 32;
        float hv = __bfloat162float(hh[base + k]) + __bfloat162float(hl[base + k]);
#pragma unroll
        for (int j = 0; j < 8; j++) acc[j] = fmaf(hv, swp[j * 512 + k], acc[j]);
    }
#pragma unroll
    for (int o = 16; o > 0; o >>= 1)
#pragma unroll
        for (int j = 0; j < 8; j++) acc[j] += __shfl_xor_sync(0xffffffffu, acc[j], o);
    if (lane == 0) {
#pragma unroll
        for (int h = 0; h < 4; h++) {
            asrc[warp * 4 + h] = acc[h];
            adst[warp * 4 + h] = acc[4 + h];
        }
    }
}

// ---------------- CSR build ----------------
__global__ void zero_int_kernel(int* p, int n)
{
    int i = blockIdx.x * blockDim.x + threadIdx.x;
    if (i < n) p[i] = 0;
}
__global__ void count_kernel(const int* __restrict__ dst, int* __restrict__ deg, int e)
{
    int i = blockIdx.x * blockDim.x + threadIdx.x;
    if (i < e) atomicAdd(&deg[dst[i]], 1);
}
__global__ void scan_kernel(const int* __restrict__ deg, int* __restrict__ rowptr, int n)
{
    __shared__ int wsum[32];
    __shared__ int carry_s;
    int tid = threadIdx.x, lane = tid & 31, wid = tid >> 5;
    if (tid == 0) carry_s = 0;
    __syncthreads();
    for (int base = 0; base < n; base += 1024) {
        int i = base + tid;
        int v = (i < n) ? deg[i] : 0;
        int s = v;
#pragma unroll
        for (int o = 1; o < 32; o <<= 1) {
            int t = __shfl_up_sync(0xffffffffu, s, o);
            if (lane >= o) s += t;
        }
        if (lane == 31) wsum[wid] = s;
        __syncthreads();
        if (wid == 0) {
            int ws = wsum[lane];
#pragma unroll
            for (int o = 1; o < 32; o <<= 1) {
                int t = __shfl_up_sync(0xffffffffu, ws, o);
                if (lane >= o) ws += t;
            }
            wsum[lane] = ws;
        }
        __syncthreads();
        int pre = (wid > 0) ? wsum[wid - 1] : 0;
        if (i < n) rowptr[i] = carry_s + pre + s - v;
        __syncthreads();
        if (tid == 0) carry_s += wsum[31];
        __syncthreads();
    }
    if (threadIdx.x == 0) rowptr[n] = carry_s;
}
__global__ void scatter_kernel(const int* __restrict__ src, const int* __restrict__ dst,
                               const int* __restrict__ rowptr, int* __restrict__ cursor,
                               int* __restrict__ csr, int e)
{
    int i = blockIdx.x * blockDim.x + threadIdx.x;
    if (i < e) {
        int d = dst[i];
        int pos = rowptr[d] + atomicAdd(&cursor[d], 1);
        csr[pos] = src[i];
    }
}

// ---------------- GAT aggregation ----------------
__device__ __forceinline__ float leaky(float v) { return v > 0.f ? v : NEG_SLOPE * v; }

__global__ void __launch_bounds__(256)
agg_kernel(const int* __restrict__ rowptr, const int* __restrict__ csr,
           const float* __restrict__ a_src, const float* __restrict__ a_dst,
           const float* __restrict__ xs, int ldx,
           const float* __restrict__ lin, int ldl,
           __nv_bfloat16* __restrict__ out_h, __nv_bfloat16* __restrict__ out_l)
{
    int warp = (blockIdx.x * blockDim.x + threadIdx.x) >> 5;
    int lane = threadIdx.x & 31;
    if (warp >= NN) return;
    const int node = warp;
    const int beg = rowptr[node];
    const int end = rowptr[node + 1];

    const float ad0 = a_dst[node * 4 + 0];
    const float ad1 = a_dst[node * 4 + 1];
    const float ad2 = a_dst[node * 4 + 2];
    const float ad3 = a_dst[node * 4 + 3];

    float m0 = -1e30f, m1 = -1e30f, m2 = -1e30f, m3 = -1e30f;
    for (int i = beg + lane; i < end; i += 32) {
        int s = csr[i];
        const float* ap = a_src + (size_t)s * 4;
        m0 = fmaxf(m0, leaky(ap[0] + ad0));
        m1 = fmaxf(m1, leaky(ap[1] + ad1));
        m2 = fmaxf(m2, leaky(ap[2] + ad2));
        m3 = fmaxf(m3, leaky(ap[3] + ad3));
    }
#pragma unroll
    for (int o = 16; o > 0; o >>= 1) {
        m0 = fmaxf(m0, __shfl_xor_sync(0xffffffffu, m0, o));
        m1 = fmaxf(m1, __shfl_xor_sync(0xffffffffu, m1, o));
        m2 = fmaxf(m2, __shfl_xor_sync(0xffffffffu, m2, o));
        m3 = fmaxf(m3, __shfl_xor_sync(0xffffffffu, m3, o));
    }

    float s0 = 0.f, s1 = 0.f, s2 = 0.f, s3 = 0.f;
    for (int i = beg + lane; i < end; i += 32) {
        int s = csr[i];
        const float* ap = a_src + (size_t)s * 4;
        s0 += expf(leaky(ap[0] + ad0) - m0);
        s1 += expf(leaky(ap[1] + ad1) - m1);
        s2 += expf(leaky(ap[2] + ad2) - m2);
        s3 += expf(leaky(ap[3] + ad3) - m3);
    }
#pragma unroll
    for (int o = 16; o > 0; o >>= 1) {
        s0 += __shfl_xor_sync(0xffffffffu, s0, o);
        s1 += __shfl_xor_sync(0xffffffffu, s1, o);
        s2 += __shfl_xor_sync(0xffffffffu, s2, o);
        s3 += __shfl_xor_sync(0xffffffffu, s3, o);
    }

    const int myh = lane >> 3;
    const float m_my   = (myh < 2) ? (myh == 0 ? m0 : m1) : (myh == 2 ? m2 : m3);
    const float sum_my = (myh < 2) ? (myh == 0 ? s0 : s1) : (myh == 2 ? s2 : s3);
    const float ad_my  = (myh < 2) ? (myh == 0 ? ad0 : ad1) : (myh == 2 ? ad2 : ad3);
    const float inv_my = 1.f / (sum_my + 1e-16f);

    float4 acc0 = make_float4(0.f, 0.f, 0.f, 0.f);
    float4 acc1 = acc0, acc2 = acc0, acc3 = acc0;

    for (int i = beg; i < end; i++) {
        int s = csr[i];
        float v = leaky(a_src[(size_t)s * 4 + myh] + ad_my);
        float w = expf(v - m_my) * inv_my;
        const float4* xp = (const float4*)(xs + (size_t)s * ldx + lane * 16);
        float4 x0 = xp[0], x1 = xp[1], x2 = xp[2], x3 = xp[3];
        acc0.x = fmaf(w, x0.x, acc0.x); acc0.y = fmaf(w, x0.y, acc0.y);
        acc0.z = fmaf(w, x0.z, acc0.z); acc0.w = fmaf(w, x0.w, acc0.w);
        acc1.x = fmaf(w, x1.x, acc1.x); acc1.y = fmaf(w, x1.y, acc1.y);
        acc1.z = fmaf(w, x1.z, acc1.z); acc1.w = fmaf(w, x1.w, acc1.w);
        acc2.x = fmaf(w, x2.x, acc2.x); acc2.y = fmaf(w, x2.y, acc2.y);
        acc2.z = fmaf(w, x2.z, acc2.z); acc2.w = fmaf(w, x2.w, acc2.w);
        acc3.x = fmaf(w, x3.x, acc3.x); acc3.y = fmaf(w, x3.y, acc3.y);
        acc3.z = fmaf(w, x3.z, acc3.z); acc3.w = fmaf(w, x3.w, acc3.w);
    }

    const float4* lp = (const float4*)(lin + (size_t)node * ldl + lane * 16);
    float4 l0 = lp[0], l1 = lp[1], l2 = lp[2], l3 = lp[3];
    float r[16];
    r[0]  = fmaxf(acc0.x + l0.x, 0.f); r[1]  = fmaxf(acc0.y + l0.y, 0.f);
    r[2]  = fmaxf(acc0.z + l0.z, 0.f); r[3]  = fmaxf(acc0.w + l0.w, 0.f);
    r[4]  = fmaxf(acc1.x + l1.x, 0.f); r[5]  = fmaxf(acc1.y + l1.y, 0.f);
    r[6]  = fmaxf(acc1.z + l1.z, 0.f); r[7]  = fmaxf(acc1.w + l1.w, 0.f);
    r[8]  = fmaxf(acc2.x + l2.x, 0.f); r[9]  = fmaxf(acc2.y + l2.y, 0.f);
    r[10] = fmaxf(acc2.z + l2.z, 0.f); r[11] = fmaxf(acc2.w + l2.w, 0.f);
    r[12] = fmaxf(acc3.x + l3.x, 0.f); r[13] = fmaxf(acc3.y + l3.y, 0.f);
    r[14] = fmaxf(acc3.z + l3.z, 0.f); r[15] = fmaxf(acc3.w + l3.w, 0.f);

    size_t base = (size_t)node * HD + lane * 16;
#pragma unroll
    for (int j = 0; j < 16; j++) {
        __nv_bfloat16 h = __float2bfloat16(r[j]);
        out_h[base + j] = h;
        out_l[base + j] = __float2bfloat16(r[j] - __bfloat162float(h));
    }
}

// ---------------- host ----------------
static void tgemm(const __nv_bfloat16* Ah, const __nv_bfloat16* Al, int lda,
                  const __nv_bfloat16* Bh, const __nv_bfloat16* Bl, int ldb,
                  float* C, int ldc,
                  __nv_bfloat16* Chi, __nv_bfloat16* Clo, int ldhl,
                  int M, int N, int Npad, int nchunks,
                  const float* b1, const float* b2, int relu)
{
    dim3 grid(Npad / 128, MTILES);
    tc_gemm<<<grid, 256, GEMM_SMEM>>>(Ah, Al, lda, Bh, Bl, ldb, C, ldc,
                                      Chi, Clo, ldhl, M, N, nchunks, b1, b2, relu);
}

template <typename T>
static T* sym(T* s) { void* p = nullptr; cudaGetSymbolAddress(&p, (const void*)s); return (T*)p; }

extern "C" void kernel_launch(void* const* d_in, const int* in_sizes, int n_in,
                              void* d_out, int out_size)
{
    const float* x      = (const float*)d_in[0];
    const int*   ei     = (const int*)d_in[1];
    const float* W_rna  = (const float*)d_in[2];
    const float* b_rna  = (const float*)d_in[3];
    const float* W_prot = (const float*)d_in[4];
    const float* b_prot = (const float*)d_in[5];
    const float* g1_ws  = (const float*)d_in[6];
    const float* g1_wd  = (const float*)d_in[7];
    const float* g1_as  = (const float*)d_in[8];
    const float* g1_ad  = (const float*)d_in[9];
    const float* g1_b   = (const float*)d_in[10];
    const float* l1_w   = (const float*)d_in[11];
    const float* l1_b   = (const float*)d_in[12];
    const float* g2_ws  = (const float*)d_in[13];
    const float* g2_wd  = (const float*)d_in[14];
    const float* g2_as  = (const float*)d_in[15];
    const float* g2_ad  = (const float*)d_in[16];
    const float* g2_b   = (const float*)d_in[17];
    const float* l2_w   = (const float*)d_in[18];
    const float* l2_b   = (const float*)d_in[19];
    const float* agg_w  = (const float*)d_in[20];
    const float* agg_b  = (const float*)d_in[21];
    const float* dr_w   = (const float*)d_in[22];
    const float* dr_b   = (const float*)d_in[23];
    const float* dp_w   = (const float*)d_in[24];
    const float* dp_b   = (const float*)d_in[25];
    const float* rr_w   = (const float*)d_in[26];
    const float* rr_b   = (const float*)d_in[27];
    const float* rp_w   = (const float*)d_in[28];
    const float* rp_b   = (const float*)d_in[29];

    float* out = (float*)d_out;
    float* out_rna  = out;
    float* out_prot = out + (size_t)NN * RNA;
    float* out_emb  = out + (size_t)NN * (RNA + PROT);

    cudaFuncSetAttribute(tc_gemm, cudaFuncAttributeMaxDynamicSharedMemorySize, GEMM_SMEM);

    __nv_bfloat16 *xr_h = sym(g_xr_h), *xr_l = sym(g_xr_l);
    __nv_bfloat16 *xp_h = sym(g_xp_h), *xp_l = sym(g_xp_l);
    __nv_bfloat16 *hh = sym(g_hh), *hl = sym(g_hl);
    __nv_bfloat16 *eh = sym(g_eh), *el = sym(g_el);
    __nv_bfloat16 *rdh = sym(g_rdh), *rdl = sym(g_rdl);
    float *xslin = sym(g_xslin);
    float *asrc = sym(g_asrc), *adst = sym(g_adst);
    float *wp1 = sym(g_wp1), *wp2 = sym(g_wp2);
    float *bcat1 = sym(g_bcat1), *bcat2 = sym(g_bcat2), *bcatd = sym(g_bcatd);
    int *deg = sym(g_deg), *cur = sym(g_cursor), *rowptr = sym(g_rowptr), *csr = sym(g_csr);

    __nv_bfloat16 *wr_h = sym(g_wr_h), *wr_l = sym(g_wr_l);
    __nv_bfloat16 *wp_h = sym(g_wp_h), *wp_l = sym(g_wp_l);
    __nv_bfloat16 *wc1_h = sym(g_wc1_h), *wc1_l = sym(g_wc1_l);
    __nv_bfloat16 *wc2_h = sym(g_wc2_h), *wc2_l = sym(g_wc2_l);
    __nv_bfloat16 *wagg_h = sym(g_wagg_h), *wagg_l = sym(g_wagg_l);
    __nv_bfloat16 *wdc_h = sym(g_wdc_h), *wdc_l = sym(g_wdc_l);
    __nv_bfloat16 *wrr_h = sym(g_wrr_h), *wrr_l = sym(g_wrr_l);
    __nv_bfloat16 *wrp_h = sym(g_wrp_h), *wrp_l = sym(g_wrp_l);

    const int* e_src = ei;
    const int* e_dst = ei + EE;

    // CSR build
    int nbN = (NN + 255) / 256;
    int nbE = (EE + 255) / 256;
    zero_int_kernel<<<nbN, 256>>>(deg, NN);
    zero_int_kernel<<<nbN, 256>>>(cur, NN);
    count_kernel<<<nbE, 256>>>(e_dst, deg, EE);
    scan_kernel<<<1, 1024>>>(deg, rowptr, NN);
    scatter_kernel<<<nbE, 256>>>(e_src, e_dst, rowptr, cur, csr, EE);

    // input splits
    {
        long t1 = (long)MPAD * 2048;
        split_kernel<<<(unsigned)((t1 + 255) / 256), 256>>>(x, INF, 0, NN, RNA, 2048, xr_h, xr_l, t1);
        long t2 = (long)MPAD * 128;
        split_kernel<<<(unsigned)((t2 + 255) / 256), 256>>>(x, INF, RNA, NN, PROT, 128, xp_h, xp_l, t2);
    }

    // weight transposes+splits (concatenated layouts)
    #define TSPLIT(W, K, N_, Kp, Np, H, L) \
        tsplit_kernel<<<(unsigned)(((long)(Np) * (Kp) + 255) / 256), 256>>>(W, K, N_, Kp, Np, H, L)
    TSPLIT(W_rna,  RNA,  EMB, 2048, 256, wr_h,  wr_l);
    TSPLIT(W_prot, PROT, EMB, 128,  256, wp_h,  wp_l);
    TSPLIT(g1_ws, HD, HD, 512, 512, wc1_h,             wc1_l);
    TSPLIT(l1_w,  HD, HD, 512, 512, wc1_h + 512 * 512, wc1_l + 512 * 512);
    TSPLIT(g2_ws, HD, HD, 512, 512, wc2_h,             wc2_l);
    TSPLIT(l2_w,  HD, HD, 512, 512, wc2_h + 512 * 512, wc2_l + 512 * 512);
    TSPLIT(agg_w, HD, HID, 512, 128, wagg_h, wagg_l);
    TSPLIT(dr_w, HID, EMB, 128, 256, wdc_h,             wdc_l);
    TSPLIT(dp_w, HID, EMB, 128, 256, wdc_h + 256 * 128, wdc_l + 256 * 128);
    TSPLIT(rr_w, EMB, RNA, 256, 2048, wrr_h, wrr_l);
    TSPLIT(rp_w, EMB, PROT, 256, 128, wrp_h, wrp_l);

    // bias concats + attention projections
    biascat_layer_kernel<<<4, 256>>>(l1_b, g1_b, bcat1);
    biascat_layer_kernel<<<4, 256>>>(l2_b, g2_b, bcat2);
    biascat_dec_kernel<<<2, 256>>>(dr_b, dp_b, bcatd);
    wproj_kernel<<<2, 256>>>(g1_ws, g1_wd, g1_as, g1_ad, wp1);
    wproj_kernel<<<2, 256>>>(g2_ws, g2_wd, g2_as, g2_ad, wp2);

    // input embeddings -> hh/hl [N x 512]
    tgemm(xr_h, xr_l, 2048, wr_h, wr_l, 2048, nullptr, 0, hh, hl, 512,
          NN, 256, 256, 32, b_rna, nullptr, 0);
    tgemm(xp_h, xp_l, 128, wp_h, wp_l, 128, nullptr, 0, hh + 256, hl + 256, 512,
          NN, 256, 256, 2, b_prot, nullptr, 0);

    const int nAgg = (NN * 32 + 255) / 256;
    const int nCoef = (NN * 32 + 255) / 256;

    // GAT layer 1: fused [xs|lin] GEMM, coef projections, aggregation
    tgemm(hh, hl, 512, wc1_h, wc1_l, 512, xslin, 1024, nullptr, nullptr, 0,
          NN, 1024, 1024, 8, bcat1, nullptr, 0);
    coef_kernel<<<nCoef, 256>>>(hh, hl, wp1, asrc, adst);
    agg_kernel<<<nAgg, 256>>>(rowptr, csr, asrc, adst, xslin, 1024, xslin + 512, 1024, hh, hl);

    // GAT layer 2
    tgemm(hh, hl, 512, wc2_h, wc2_l, 512, xslin, 1024, nullptr, nullptr, 0,
          NN, 1024, 1024, 8, bcat2, nullptr, 0);
    coef_kernel<<<nCoef, 256>>>(hh, hl, wp2, asrc, adst);
    agg_kernel<<<nAgg, 256>>>(rowptr, csr, asrc, adst, xslin, 1024, xslin + 512, 1024, hh, hl);

    // embedding = relu(h @ agg_w + agg_b): fp32 -> out_emb, hi/lo -> eh/el
    tgemm(hh, hl, 512, wagg_h, wagg_l, 512, out_emb, HID, eh, el, 128,
          NN, HID, 128, 8, agg_b, nullptr, 1);

    // decoders (fused): rd = [emb@dr_w+dr_b | emb@dp_w+dp_b] -> rdh/rdl [N x 512]
    tgemm(eh, el, 128, wdc_h, wdc_l, 128, nullptr, 0, rdh, rdl, 512,
          NN, 512, 512, 2, bcatd, nullptr, 0);

    // reconstructions
    tgemm(rdh, rdl, 512, wrr_h, wrr_l, 256, out_rna, RNA, nullptr, nullptr, 0,
          NN, RNA, 2048, 4, rr_b, nullptr, 0);
    tgemm(rdh + 256, rdl + 256, 512, wrp_h, wrp_l, 256, out_prot, PROT, nullptr, nullptr, 0,
          NN, PROT, 128, 4, rp_b, nullptr, 0);
}

// round 7
// speedup vs baseline: 2.3339x; 1.1602x over previous
#include <cuda_runtime.h>
#include <cuda_bf16.h>
#include <math.h>
#include <stdint.h>

#define NN     20000
#define EE     320000
#define RNA    2000
#define PROT   100
#define EMB    256
#define HID    128
#define NHEAD  4
#define HD     512
#define INF    2100
#define NEG_SLOPE 0.2f

#define MPAD   20096
#define MTILES 157

#define KCH         32
#define STAGES      3
#define STAGE_BYTES 32768                  // Ah,Al,Bh,Bl x 8KB (128 rows x 64B)
#define GEMM_SMEM   (STAGES * STAGE_BYTES) // 96KB -> 2 CTAs/SM

// ---------------- device scratch (zero-init at load) ----------------
__device__ __align__(16) __nv_bfloat16 g_hh[(size_t)MPAD * 512];
__device__ __align__(16) __nv_bfloat16 g_hl[(size_t)MPAD * 512];
__device__ __align__(16) __nv_bfloat16 g_eh[(size_t)MPAD * 128];
__device__ __align__(16) __nv_bfloat16 g_el[(size_t)MPAD * 128];
__device__ __align__(16) __nv_bfloat16 g_rdh[(size_t)MPAD * 512];
__device__ __align__(16) __nv_bfloat16 g_rdl[(size_t)MPAD * 512];

__device__ __align__(16) float g_xslin[(size_t)MPAD * 1024];
__device__ __align__(16) float g_asrc[(size_t)NN * NHEAD];
__device__ __align__(16) float g_adst[(size_t)NN * NHEAD];
__device__ __align__(16) float g_wp1[8 * 512];
__device__ __align__(16) float g_wp2[8 * 512];
__device__ __align__(16) float g_bcat1[1024];
__device__ __align__(16) float g_bcat2[1024];
__device__ __align__(16) float g_bcatd[512];

__device__ __align__(16) __nv_bfloat16 g_wr_h[256 * 2048],   g_wr_l[256 * 2048];
__device__ __align__(16) __nv_bfloat16 g_wp_h[256 * 128],    g_wp_l[256 * 128];
__device__ __align__(16) __nv_bfloat16 g_wc1_h[1024 * 512],  g_wc1_l[1024 * 512];
__device__ __align__(16) __nv_bfloat16 g_wc2_h[1024 * 512],  g_wc2_l[1024 * 512];
__device__ __align__(16) __nv_bfloat16 g_wagg_h[128 * 512],  g_wagg_l[128 * 512];
__device__ __align__(16) __nv_bfloat16 g_wdc_h[512 * 128],   g_wdc_l[512 * 128];
__device__ __align__(16) __nv_bfloat16 g_wrr_h[2048 * 256],  g_wrr_l[2048 * 256];
__device__ __align__(16) __nv_bfloat16 g_wrp_h[128 * 256],   g_wrp_l[128 * 256];

__device__ int g_deg[NN];
__device__ int g_cursor[NN];
__device__ int g_rowptr[NN + 1];
__device__ int g_csr[EE];

// ---------------- PTX helpers ----------------
__device__ __forceinline__ uint32_t smem_u32(const void* p) {
    uint32_t a;
    asm("{ .reg .u64 t; cvta.to.shared.u64 t, %1; cvt.u32.u64 %0, t; }" : "=r"(a) : "l"(p));
    return a;
}
__device__ __forceinline__ void cp16(uint32_t dst, const void* src) {
    asm volatile("cp.async.cg.shared.global [%0], [%1], 16;" :: "r"(dst), "l"(src));
}
// predicated: src-size 0 -> zero fill
__device__ __forceinline__ void cp16p(uint32_t dst, const void* src, bool ok) {
    int sz = ok ? 16 : 0;
    asm volatile("cp.async.cg.shared.global [%0], [%1], 16, %2;"
                 :: "r"(dst), "l"(src), "r"(sz));
}
#define CP_COMMIT() asm volatile("cp.async.commit_group;" ::: "memory")
#define CP_WAIT(n)  asm volatile("cp.async.wait_group %0;" :: "n"(n) : "memory")

__device__ __forceinline__ uint32_t swz64(uint32_t off) {
    return off ^ ((off >> 3) & 0x30);
}
__device__ __forceinline__ void ldm_x4(uint32_t addr, uint32_t r[4]) {
    asm volatile("ldmatrix.sync.aligned.m8n8.x4.shared.b16 {%0,%1,%2,%3}, [%4];"
                 : "=r"(r[0]), "=r"(r[1]), "=r"(r[2]), "=r"(r[3]) : "r"(addr));
}
__device__ __forceinline__ void mma_bf16(float c[4], const uint32_t a[4],
                                         uint32_t b0, uint32_t b1) {
    asm volatile(
        "mma.sync.aligned.m16n8k16.row.col.f32.bf16.bf16.f32 "
        "{%0,%1,%2,%3}, {%4,%5,%6,%7}, {%8,%9}, {%0,%1,%2,%3};"
        : "+f"(c[0]), "+f"(c[1]), "+f"(c[2]), "+f"(c[3])
        : "r"(a[0]), "r"(a[1]), "r"(a[2]), "r"(a[3]), "r"(b0), "r"(b1));
}
__device__ __forceinline__ uint32_t pack_bf16x2(float a, float b) {
    __nv_bfloat162 t = __floats2bfloat162_rn(a, b);
    return *(uint32_t*)&t;
}

// ---------------- warp-MMA GEMM ----------------
// 128x128 tile/CTA, K-chunks of 32 (SW64 swizzle), 3 stages, 2 CTAs/SM.
// Mode A (Afp==null): A given as bf16 hi/lo arrays.
// Mode B (Afp!=null): fp32 A read directly (lda = fp32 row stride), converted
// to bf16 hi/lo in smem; rows >= M and cols >= Kvalid zero-filled.
__device__ __forceinline__ void load_bf16(
    uint32_t sb,
    const __nv_bfloat16* __restrict__ Ah, const __nv_bfloat16* __restrict__ Al, int lda,
    const __nv_bfloat16* __restrict__ Bh, const __nv_bfloat16* __restrict__ Bl, int ldb,
    int row0, int col0, int kOff, int tid)
{
#pragma unroll
    for (int j = 0; j < 8; j++) {
        int g = tid + j * 256;          // 0..2047
        int sub = g >> 9;               // 0:Ah 1:Al 2:Bh 3:Bl
        int r = (g >> 2) & 127;
        int q = g & 3;
        const __nv_bfloat16* src;
        if (sub == 0)      src = Ah + (size_t)(row0 + r) * lda + kOff + q * 8;
        else if (sub == 1) src = Al + (size_t)(row0 + r) * lda + kOff + q * 8;
        else if (sub == 2) src = Bh + (size_t)(col0 + r) * ldb + kOff + q * 8;
        else               src = Bl + (size_t)(col0 + r) * ldb + kOff + q * 8;
        cp16(sb + (uint32_t)sub * 8192 + swz64((uint32_t)(r * 64 + q * 16)), src);
    }
}

__device__ __forceinline__ void load_f32(
    uint32_t sb,
    const float* __restrict__ Afp, int lda, int M, int Kvalid,
    const __nv_bfloat16* __restrict__ Bh, const __nv_bfloat16* __restrict__ Bl, int ldb,
    int row0, int col0, int kOff, int tid)
{
#pragma unroll
    for (int j = 0; j < 8; j++) {
        int g = tid + j * 256;
        if (g < 1024) {                 // fp32 A tile: 128 rows x 8 quads (16B)
            int r = g >> 3;
            int q = g & 7;
            bool ok = (row0 + r < M) && (kOff + q * 4 < Kvalid);
            const float* src = Afp + (size_t)(row0 + r) * lda + kOff + q * 4;
            cp16p(sb + (uint32_t)(r * 128 + q * 16), ok ? src : Afp, ok);
        } else {
            int g2 = g - 1024;
            int sub = g2 >> 9;          // 0:Bh 1:Bl
            int r = (g2 >> 2) & 127;
            int q = g2 & 3;
            const __nv_bfloat16* src = (sub == 0 ? Bh : Bl)
                                     + (size_t)(col0 + r) * ldb + kOff + q * 8;
            cp16(sb + 16384u + (uint32_t)sub * 8192 + swz64((uint32_t)(r * 64 + q * 16)), src);
        }
    }
}

// in-place fp32 -> bf16 hi/lo conversion of a stage's A region (16KB)
__device__ __forceinline__ void convert_a(char* smem, uint32_t stoff, int tid)
{
    float4 v[4];
    const char* base = smem + stoff;
#pragma unroll
    for (int i = 0; i < 4; i++)
        v[i] = *(const float4*)(base + tid * 16 + i * 4096);
    __syncthreads();
#pragma unroll
    for (int i = 0; i < 4; i++) {
        int p = i * 1024 + tid * 4;     // float index within 128x32 tile
        int row = p >> 5, k = p & 31;
        __nv_bfloat16 h0 = __float2bfloat16(v[i].x);
        __nv_bfloat16 h1 = __float2bfloat16(v[i].y);
        __nv_bfloat16 h2 = __float2bfloat16(v[i].z);
        __nv_bfloat16 h3 = __float2bfloat16(v[i].w);
        float l0 = v[i].x - __bfloat162float(h0);
        float l1 = v[i].y - __bfloat162float(h1);
        float l2 = v[i].z - __bfloat162float(h2);
        float l3 = v[i].w - __bfloat162float(h3);
        uint32_t hi01 = ((uint32_t)(*(uint16_t*)&h1) << 16) | (*(uint16_t*)&h0);
        uint32_t hi23 = ((uint32_t)(*(uint16_t*)&h3) << 16) | (*(uint16_t*)&h2);
        uint32_t lo01 = pack_bf16x2(l0, l1);
        uint32_t lo23 = pack_bf16x2(l2, l3);
        uint32_t off = swz64((uint32_t)(row * 64 + k * 2));
        *(uint2*)(smem + stoff + off)        = make_uint2(hi01, hi23);
        *(uint2*)(smem + stoff + 8192 + off) = make_uint2(lo01, lo23);
    }
    __syncthreads();
}

__global__ void __launch_bounds__(256, 2)
tc_gemm(const __nv_bfloat16* __restrict__ Ah, const __nv_bfloat16* __restrict__ Al, int lda,
        const float* __restrict__ Afp, int Kvalid,
        const __nv_bfloat16* __restrict__ Bh, const __nv_bfloat16* __restrict__ Bl, int ldb,
        float* __restrict__ C, int ldc,
        __nv_bfloat16* __restrict__ Chi, __nv_bfloat16* __restrict__ Clo, int ldhl,
        int M, int N, int nchunks,
        const float* __restrict__ bias1, const float* __restrict__ bias2, int relu)
{
    extern __shared__ char smem[];
    const uint32_t sm = smem_u32(smem);
    const int tid = threadIdx.x;
    const int wid = tid >> 5, lane = tid & 31;
    const int row0 = blockIdx.y * 128;
    const int col0 = blockIdx.x * 128;

    const int wm = wid & 1;
    const int wn = wid >> 1;
    const int li    = lane & 7;
    const int matm  = (lane >> 3) & 1;
    const int khalf = lane >> 4;

    float acc[4][4][4];
#pragma unroll
    for (int a = 0; a < 4; a++)
#pragma unroll
        for (int b = 0; b < 4; b++)
#pragma unroll
            for (int c = 0; c < 4; c++) acc[a][b][c] = 0.f;

#define LOADC(cc) do { \
    uint32_t sbl = sm + (uint32_t)((cc) % STAGES) * STAGE_BYTES; \
    if (Afp) load_f32(sbl, Afp, lda, M, Kvalid, Bh, Bl, ldb, row0, col0, (cc) * KCH, tid); \
    else     load_bf16(sbl, Ah, Al, lda, Bh, Bl, ldb, row0, col0, (cc) * KCH, tid); \
} while (0)

    LOADC(0); CP_COMMIT();
    if (nchunks > 1) { LOADC(1); CP_COMMIT(); }

    for (int c = 0; c < nchunks; c++) {
        const uint32_t sb = sm + (uint32_t)(c % STAGES) * STAGE_BYTES;
        if (c + 2 < nchunks) {
            LOADC(c + 2); CP_COMMIT(); CP_WAIT(2);
        } else if (c + 1 < nchunks) {
            CP_WAIT(1);
        } else {
            CP_WAIT(0);
        }
        __syncthreads();

        if (Afp) convert_a(smem, (uint32_t)((c % STAGES) * STAGE_BYTES), tid);

#pragma unroll
        for (int ks = 0; ks < 2; ks++) {
            const int kb = ks * 32 + khalf * 16;
            uint32_t bh[2][4], bl[2][4];
#pragma unroll
            for (int nj = 0; nj < 2; nj++) {
                const int r = wn * 32 + nj * 16 + matm * 8 + li;
                const uint32_t off = swz64((uint32_t)(r * 64 + kb));
                ldm_x4(sb + 16384 + off, bh[nj]);
                ldm_x4(sb + 24576 + off, bl[nj]);
            }
#pragma unroll
            for (int mi = 0; mi < 4; mi++) {
                const int r = wm * 64 + mi * 16 + matm * 8 + li;
                const uint32_t off = swz64((uint32_t)(r * 64 + kb));
                uint32_t a[4];
                ldm_x4(sb + off, a);            // Ah
#pragma unroll
                for (int ni = 0; ni < 4; ni++) {
                    const int nj = ni >> 1, s = ni & 1;
                    mma_bf16(acc[mi][ni], a, bh[nj][s], bh[nj][s + 2]);
                }
#pragma unroll
                for (int ni = 0; ni < 4; ni++) {
                    const int nj = ni >> 1, s = ni & 1;
                    mma_bf16(acc[mi][ni], a, bl[nj][s], bl[nj][s + 2]);
                }
                ldm_x4(sb + 8192 + off, a);     // Al
#pragma unroll
                for (int ni = 0; ni < 4; ni++) {
                    const int nj = ni >> 1, s = ni & 1;
                    mma_bf16(acc[mi][ni], a, bh[nj][s], bh[nj][s + 2]);
                }
            }
        }
        __syncthreads();
    }
#undef LOADC

    // epilogue: acc -> smem fp32 (stride 132) -> coalesced global
    float* eps = (float*)smem;
    const int grp = lane >> 2, qp = lane & 3;
#pragma unroll
    for (int mi = 0; mi < 4; mi++) {
#pragma unroll
        for (int ni = 0; ni < 4; ni++) {
            const int r = wm * 64 + mi * 16 + grp;
            const int col = wn * 32 + ni * 8 + qp * 2;
            eps[r * 132 + col]           = acc[mi][ni][0];
            eps[r * 132 + col + 1]       = acc[mi][ni][1];
            eps[(r + 8) * 132 + col]     = acc[mi][ni][2];
            eps[(r + 8) * 132 + col + 1] = acc[mi][ni][3];
        }
    }
    __syncthreads();

#pragma unroll
    for (int i = 0; i < 16; i++) {
        const int f = tid + i * 256;
        const int r = f >> 5, c4 = f & 31;
        const int grow = row0 + r;
        const int col = col0 + c4 * 4;
        if (grow >= M || col >= N) continue;
        float v[4];
#pragma unroll
        for (int j = 0; j < 4; j++) {
            v[j] = eps[r * 132 + c4 * 4 + j];
            const int cc = col + j;
            if (cc < N) {
                if (bias1) v[j] += bias1[cc];
                if (bias2) v[j] += bias2[cc];
                if (relu)  v[j] = fmaxf(v[j], 0.f);
            }
        }
        if (C) {
            if (col + 3 < N) {
                *(float4*)(C + (size_t)grow * ldc + col) = make_float4(v[0], v[1], v[2], v[3]);
            } else {
#pragma unroll
                for (int j = 0; j < 4; j++)
                    if (col + j < N) C[(size_t)grow * ldc + col + j] = v[j];
            }
        }
        if (Chi) {
#pragma unroll
            for (int j = 0; j < 4; j++) {
                if (col + j < N) {
                    __nv_bfloat16 h = __float2bfloat16(v[j]);
                    Chi[(size_t)grow * ldhl + col + j] = h;
                    Clo[(size_t)grow * ldhl + col + j] =
                        __float2bfloat16(v[j] - __bfloat162float(h));
                }
            }
        }
    }
}

// ---------------- conversions / small kernels ----------------
__global__ void tsplit_kernel(const float* __restrict__ W, int K, int N,
                              int Kpad, int Npad,
                              __nv_bfloat16* __restrict__ h, __nv_bfloat16* __restrict__ l)
{
    long idx = (long)blockIdx.x * blockDim.x + threadIdx.x;
    long total = (long)Npad * Kpad;
    if (idx >= total) return;
    int n = (int)(idx / Kpad);
    int k = (int)(idx % Kpad);
    float v = 0.f;
    if (n < N && k < K) v = W[(size_t)k * N + n];
    __nv_bfloat16 hi = __float2bfloat16(v);
    h[idx] = hi;
    l[idx] = __float2bfloat16(v - __bfloat162float(hi));
}

__global__ void wproj_kernel(const float* __restrict__ ws, const float* __restrict__ wd,
                             const float* __restrict__ as_, const float* __restrict__ ad_,
                             float* __restrict__ wp)
{
    int k = blockIdx.x * blockDim.x + threadIdx.x;
    if (k >= 512) return;
#pragma unroll
    for (int h = 0; h < 4; h++) {
        float s1 = 0.f, s2 = 0.f;
        for (int d = 0; d < 128; d++) {
            s1 = fmaf(ws[(size_t)k * 512 + h * 128 + d], as_[h * 128 + d], s1);
            s2 = fmaf(wd[(size_t)k * 512 + h * 128 + d], ad_[h * 128 + d], s2);
        }
        wp[h * 512 + k] = s1;
        wp[(4 + h) * 512 + k] = s2;
    }
}

__global__ void biascat_layer_kernel(const float* __restrict__ lb, const float* __restrict__ gb,
                                     float* __restrict__ out)
{
    int i = blockIdx.x * blockDim.x + threadIdx.x;
    if (i < 512) out[i] = 0.f;
    else if (i < 1024) out[i] = lb[i - 512] + gb[i - 512];
}
__global__ void biascat_dec_kernel(const float* __restrict__ a, const float* __restrict__ b,
                                   float* __restrict__ out)
{
    int i = blockIdx.x * blockDim.x + threadIdx.x;
    if (i < 256) out[i] = a[i];
    else if (i < 512) out[i] = b[i - 256];
}

__global__ void __launch_bounds__(256)
coef_kernel(const __nv_bfloat16* __restrict__ hh, const __nv_bfloat16* __restrict__ hl,
            const float* __restrict__ wp,
            float* __restrict__ asrc, float* __restrict__ adst)
{
    __shared__ float swp[8 * 512];
    for (int i = threadIdx.x; i < 8 * 512; i += blockDim.x) swp[i] = wp[i];
    __syncthreads();
    int warp = (blockIdx.x * blockDim.x + threadIdx.x) >> 5;
    int lane = threadIdx.x & 31;
    if (warp >= NN) return;
    float acc[8] = {0.f, 0.f, 0.f, 0.f, 0.f, 0.f, 0.f, 0.f};
    const size_t base = (size_t)warp * 512;
#pragma unroll
    for (int i = 0; i < 16; i++) {
        int k = lane + i * 32;
        float hv = __bfloat162float(hh[base + k]) + __bfloat162float(hl[base + k]);
#pragma unroll
        for (int j = 0; j < 8; j++) acc[j] = fmaf(hv, swp[j * 512 + k], acc[j]);
    }
#pragma unroll
    for (int o = 16; o > 0; o >>= 1)
#pragma unroll
        for (int j = 0; j < 8; j++) acc[j] += __shfl_xor_sync(0xffffffffu, acc[j], o);
    if (lane == 0) {
#pragma unroll
        for (int h = 0; h < 4; h++) {
            asrc[warp * 4 + h] = acc[h];
            adst[warp * 4 + h] = acc[4 + h];
        }
    }
}

// ---------------- CSR build ----------------
__global__ void zero_int_kernel(int* p, int n)
{
    int i = blockIdx.x * blockDim.x + threadIdx.x;
    if (i < n) p[i] = 0;
}
__global__ void count_kernel(const int* __restrict__ dst, int* __restrict__ deg, int e)
{
    int i = blockIdx.x * blockDim.x + threadIdx.x;
    if (i < e) atomicAdd(&deg[dst[i]], 1);
}
__global__ void scan_kernel(const int* __restrict__ deg, int* __restrict__ rowptr, int n)
{
    __shared__ int wsum[32];
    __shared__ int carry_s;
    int tid = threadIdx.x, lane = tid & 31, wid = tid >> 5;
    if (tid == 0) carry_s = 0;
    __syncthreads();
    for (int base = 0; base < n; base += 1024) {
        int i = base + tid;
        int v = (i < n) ? deg[i] : 0;
        int s = v;
#pragma unroll
        for (int o = 1; o < 32; o <<= 1) {
            int t = __shfl_up_sync(0xffffffffu, s, o);
            if (lane >= o) s += t;
        }
        if (lane == 31) wsum[wid] = s;
        __syncthreads();
        if (wid == 0) {
            int ws = wsum[lane];
#pragma unroll
            for (int o = 1; o < 32; o <<= 1) {
                int t = __shfl_up_sync(0xffffffffu, ws, o);
                if (lane >= o) ws += t;
            }
            wsum[lane] = ws;
        }
        __syncthreads();
        int pre = (wid > 0) ? wsum[wid - 1] : 0;
        if (i < n) rowptr[i] = carry_s + pre + s - v;
        __syncthreads();
        if (tid == 0) carry_s += wsum[31];
        __syncthreads();
    }
    if (threadIdx.x == 0) rowptr[n] = carry_s;
}
__global__ void scatter_kernel(const int* __restrict__ src, const int* __restrict__ dst,
                               const int* __restrict__ rowptr, int* __restrict__ cursor,
                               int* __restrict__ csr, int e)
{
    int i = blockIdx.x * blockDim.x + threadIdx.x;
    if (i < e) {
        int d = dst[i];
        int pos = rowptr[d] + atomicAdd(&cursor[d], 1);
        csr[pos] = src[i];
    }
}

// ---------------- GAT aggregation ----------------
__device__ __forceinline__ float leaky(float v) { return v > 0.f ? v : NEG_SLOPE * v; }

__global__ void __launch_bounds__(256)
agg_kernel(const int* __restrict__ rowptr, const int* __restrict__ csr,
           const float* __restrict__ a_src, const float* __restrict__ a_dst,
           const float* __restrict__ xs, int ldx,
           const float* __restrict__ lin, int ldl,
           __nv_bfloat16* __restrict__ out_h, __nv_bfloat16* __restrict__ out_l)
{
    int warp = (blockIdx.x * blockDim.x + threadIdx.x) >> 5;
    int lane = threadIdx.x & 31;
    if (warp >= NN) return;
    const int node = warp;
    const int beg = rowptr[node];
    const int end = rowptr[node + 1];

    const float ad0 = a_dst[node * 4 + 0];
    const float ad1 = a_dst[node * 4 + 1];
    const float ad2 = a_dst[node * 4 + 2];
    const float ad3 = a_dst[node * 4 + 3];

    float m0 = -1e30f, m1 = -1e30f, m2 = -1e30f, m3 = -1e30f;
    for (int i = beg + lane; i < end; i += 32) {
        int s = csr[i];
        const float* ap = a_src + (size_t)s * 4;
        m0 = fmaxf(m0, leaky(ap[0] + ad0));
        m1 = fmaxf(m1, leaky(ap[1] + ad1));
        m2 = fmaxf(m2, leaky(ap[2] + ad2));
        m3 = fmaxf(m3, leaky(ap[3] + ad3));
    }
#pragma unroll
    for (int o = 16; o > 0; o >>= 1) {
        m0 = fmaxf(m0, __shfl_xor_sync(0xffffffffu, m0, o));
        m1 = fmaxf(m1, __shfl_xor_sync(0xffffffffu, m1, o));
        m2 = fmaxf(m2, __shfl_xor_sync(0xffffffffu, m2, o));
        m3 = fmaxf(m3, __shfl_xor_sync(0xffffffffu, m3, o));
    }

    float s0 = 0.f, s1 = 0.f, s2 = 0.f, s3 = 0.f;
    for (int i = beg + lane; i < end; i += 32) {
        int s = csr[i];
        const float* ap = a_src + (size_t)s * 4;
        s0 += expf(leaky(ap[0] + ad0) - m0);
        s1 += expf(leaky(ap[1] + ad1) - m1);
        s2 += expf(leaky(ap[2] + ad2) - m2);
        s3 += expf(leaky(ap[3] + ad3) - m3);
    }
#pragma unroll
    for (int o = 16; o > 0; o >>= 1) {
        s0 += __shfl_xor_sync(0xffffffffu, s0, o);
        s1 += __shfl_xor_sync(0xffffffffu, s1, o);
        s2 += __shfl_xor_sync(0xffffffffu, s2, o);
        s3 += __shfl_xor_sync(0xffffffffu, s3, o);
    }

    const int myh = lane >> 3;
    const float m_my   = (myh < 2) ? (myh == 0 ? m0 : m1) : (myh == 2 ? m2 : m3);
    const float sum_my = (myh < 2) ? (myh == 0 ? s0 : s1) : (myh == 2 ? s2 : s3);
    const float ad_my  = (myh < 2) ? (myh == 0 ? ad0 : ad1) : (myh == 2 ? ad2 : ad3);
    const float inv_my = 1.f / (sum_my + 1e-16f);

    float4 acc0 = make_float4(0.f, 0.f, 0.f, 0.f);
    float4 acc1 = acc0, acc2 = acc0, acc3 = acc0;

    for (int i = beg; i < end; i++) {
        int s = csr[i];
        float v = leaky(a_src[(size_t)s * 4 + myh] + ad_my);
        float w = expf(v - m_my) * inv_my;
        const float4* xp = (const float4*)(xs + (size_t)s * ldx + lane * 16);
        float4 x0 = xp[0], x1 = xp[1], x2 = xp[2], x3 = xp[3];
        acc0.x = fmaf(w, x0.x, acc0.x); acc0.y = fmaf(w, x0.y, acc0.y);
        acc0.z = fmaf(w, x0.z, acc0.z); acc0.w = fmaf(w, x0.w, acc0.w);
        acc1.x = fmaf(w, x1.x, acc1.x); acc1.y = fmaf(w, x1.y, acc1.y);
        acc1.z = fmaf(w, x1.z, acc1.z); acc1.w = fmaf(w, x1.w, acc1.w);
        acc2.x = fmaf(w, x2.x, acc2.x); acc2.y = fmaf(w, x2.y, acc2.y);
        acc2.z = fmaf(w, x2.z, acc2.z); acc2.w = fmaf(w, x2.w, acc2.w);
        acc3.x = fmaf(w, x3.x, acc3.x); acc3.y = fmaf(w, x3.y, acc3.y);
        acc3.z = fmaf(w, x3.z, acc3.z); acc3.w = fmaf(w, x3.w, acc3.w);
    }

    const float4* lp = (const float4*)(lin + (size_t)node * ldl + lane * 16);
    float4 l0 = lp[0], l1 = lp[1], l2 = lp[2], l3 = lp[3];
    float r[16];
    r[0]  = fmaxf(acc0.x + l0.x, 0.f); r[1]  = fmaxf(acc0.y + l0.y, 0.f);
    r[2]  = fmaxf(acc0.z + l0.z, 0.f); r[3]  = fmaxf(acc0.w + l0.w, 0.f);
    r[4]  = fmaxf(acc1.x + l1.x, 0.f); r[5]  = fmaxf(acc1.y + l1.y, 0.f);
    r[6]  = fmaxf(acc1.z + l1.z, 0.f); r[7]  = fmaxf(acc1.w + l1.w, 0.f);
    r[8]  = fmaxf(acc2.x + l2.x, 0.f); r[9]  = fmaxf(acc2.y + l2.y, 0.f);
    r[10] = fmaxf(acc2.z + l2.z, 0.f); r[11] = fmaxf(acc2.w + l2.w, 0.f);
    r[12] = fmaxf(acc3.x + l3.x, 0.f); r[13] = fmaxf(acc3.y + l3.y, 0.f);
    r[14] = fmaxf(acc3.z + l3.z, 0.f); r[15] = fmaxf(acc3.w + l3.w, 0.f);

    size_t base = (size_t)node * HD + lane * 16;
#pragma unroll
    for (int j = 0; j < 16; j++) {
        __nv_bfloat16 h = __float2bfloat16(r[j]);
        out_h[base + j] = h;
        out_l[base + j] = __float2bfloat16(r[j] - __bfloat162float(h));
    }
}

// ---------------- host ----------------
static void tgemm(const __nv_bfloat16* Ah, const __nv_bfloat16* Al, int lda,
                  const float* Afp, int Kvalid,
                  const __nv_bfloat16* Bh, const __nv_bfloat16* Bl, int ldb,
                  float* C, int ldc,
                  __nv_bfloat16* Chi, __nv_bfloat16* Clo, int ldhl,
                  int M, int N, int Npad, int nchunks,
                  const float* b1, const float* b2, int relu)
{
    dim3 grid(Npad / 128, MTILES);
    tc_gemm<<<grid, 256, GEMM_SMEM>>>(Ah, Al, lda, Afp, Kvalid, Bh, Bl, ldb, C, ldc,
                                      Chi, Clo, ldhl, M, N, nchunks, b1, b2, relu);
}

template <typename T>
static T* sym(T* s) { void* p = nullptr; cudaGetSymbolAddress(&p, (const void*)s); return (T*)p; }

extern "C" void kernel_launch(void* const* d_in, const int* in_sizes, int n_in,
                              void* d_out, int out_size)
{
    const float* x      = (const float*)d_in[0];
    const int*   ei     = (const int*)d_in[1];
    const float* W_rna  = (const float*)d_in[2];
    const float* b_rna  = (const float*)d_in[3];
    const float* W_prot = (const float*)d_in[4];
    const float* b_prot = (const float*)d_in[5];
    const float* g1_ws  = (const float*)d_in[6];
    const float* g1_wd  = (const float*)d_in[7];
    const float* g1_as  = (const float*)d_in[8];
    const float* g1_ad  = (const float*)d_in[9];
    const float* g1_b   = (const float*)d_in[10];
    const float* l1_w   = (const float*)d_in[11];
    const float* l1_b   = (const float*)d_in[12];
    const float* g2_ws  = (const float*)d_in[13];
    const float* g2_wd  = (const float*)d_in[14];
    const float* g2_as  = (const float*)d_in[15];
    const float* g2_ad  = (const float*)d_in[16];
    const float* g2_b   = (const float*)d_in[17];
    const float* l2_w   = (const float*)d_in[18];
    const float* l2_b   = (const float*)d_in[19];
    const float* agg_w  = (const float*)d_in[20];
    const float* agg_b  = (const float*)d_in[21];
    const float* dr_w   = (const float*)d_in[22];
    const float* dr_b   = (const float*)d_in[23];
    const float* dp_w   = (const float*)d_in[24];
    const float* dp_b   = (const float*)d_in[25];
    const float* rr_w   = (const float*)d_in[26];
    const float* rr_b   = (const float*)d_in[27];
    const float* rp_w   = (const float*)d_in[28];
    const float* rp_b   = (const float*)d_in[29];

    float* out = (float*)d_out;
    float* out_rna  = out;
    float* out_prot = out + (size_t)NN * RNA;
    float* out_emb  = out + (size_t)NN * (RNA + PROT);

    cudaFuncSetAttribute(tc_gemm, cudaFuncAttributeMaxDynamicSharedMemorySize, GEMM_SMEM);

    __nv_bfloat16 *hh = sym(g_hh), *hl = sym(g_hl);
    __nv_bfloat16 *eh = sym(g_eh), *el = sym(g_el);
    __nv_bfloat16 *rdh = sym(g_rdh), *rdl = sym(g_rdl);
    float *xslin = sym(g_xslin);
    float *asrc = sym(g_asrc), *adst = sym(g_adst);
    float *wp1 = sym(g_wp1), *wp2 = sym(g_wp2);
    float *bcat1 = sym(g_bcat1), *bcat2 = sym(g_bcat2), *bcatd = sym(g_bcatd);
    int *deg = sym(g_deg), *cur = sym(g_cursor), *rowptr = sym(g_rowptr), *csr = sym(g_csr);

    __nv_bfloat16 *wr_h = sym(g_wr_h), *wr_l = sym(g_wr_l);
    __nv_bfloat16 *wp_h = sym(g_wp_h), *wp_l = sym(g_wp_l);
    __nv_bfloat16 *wc1_h = sym(g_wc1_h), *wc1_l = sym(g_wc1_l);
    __nv_bfloat16 *wc2_h = sym(g_wc2_h), *wc2_l = sym(g_wc2_l);
    __nv_bfloat16 *wagg_h = sym(g_wagg_h), *wagg_l = sym(g_wagg_l);
    __nv_bfloat16 *wdc_h = sym(g_wdc_h), *wdc_l = sym(g_wdc_l);
    __nv_bfloat16 *wrr_h = sym(g_wrr_h), *wrr_l = sym(g_wrr_l);
    __nv_bfloat16 *wrp_h = sym(g_wrp_h), *wrp_l = sym(g_wrp_l);

    const int* e_src = ei;
    const int* e_dst = ei + EE;

    #define TSPLIT(W, K, N_, Kp, Np, H, L) \
        tsplit_kernel<<<(unsigned)(((long)(Np) * (Kp) + 255) / 256), 256>>>(W, K, N_, Kp, Np, H, L)

    const int nAgg = (NN * 32 + 255) / 256;

    // launches 1-3: weight prep (so launch 4 = big rna GEMM for ncu)
    TSPLIT(W_rna,  RNA,  EMB, 2048, 256, wr_h,  wr_l);
    TSPLIT(W_prot, PROT, EMB, 128,  256, wp_h,  wp_l);
    TSPLIT(g1_ws, HD, HD, 512, 512, wc1_h, wc1_l);

    // input embeddings straight from fp32 x (fused split); lda slot = INF
    tgemm(nullptr, nullptr, INF, x, RNA, wr_h, wr_l, 2048, nullptr, 0,
          hh, hl, 512, NN, 256, 256, (RNA + KCH - 1) / KCH, b_rna, nullptr, 0);
    tgemm(nullptr, nullptr, INF, x + RNA, PROT, wp_h, wp_l, 128, nullptr, 0,
          hh + 256, hl + 256, 512, NN, 256, 256, (PROT + KCH - 1) / KCH, b_prot, nullptr, 0);

    // GAT layer 1
    TSPLIT(l1_w, HD, HD, 512, 512, wc1_h + 512 * 512, wc1_l + 512 * 512);
    biascat_layer_kernel<<<4, 256>>>(l1_b, g1_b, bcat1);
    tgemm(hh, hl, 512, nullptr, 0, wc1_h, wc1_l, 512, xslin, 1024,
          nullptr, nullptr, 0, NN, 1024, 1024, 16, bcat1, nullptr, 0);
    wproj_kernel<<<2, 256>>>(g1_ws, g1_wd, g1_as, g1_ad, wp1);
    coef_kernel<<<nAgg, 256>>>(hh, hl, wp1, asrc, adst);
    zero_int_kernel<<<(NN + 255) / 256, 256>>>(deg, NN);
    zero_int_kernel<<<(NN + 255) / 256, 256>>>(cur, NN);
    count_kernel<<<(EE + 255) / 256, 256>>>(e_dst, deg, EE);
    scan_kernel<<<1, 1024>>>(deg, rowptr, NN);
    scatter_kernel<<<(EE + 255) / 256, 256>>>(e_src, e_dst, rowptr, cur, csr, EE);
    agg_kernel<<<nAgg, 256>>>(rowptr, csr, asrc, adst,
                              xslin, 1024, xslin + 512, 1024, hh, hl);

    // GAT layer 2
    TSPLIT(g2_ws, HD, HD, 512, 512, wc2_h, wc2_l);
    TSPLIT(l2_w,  HD, HD, 512, 512, wc2_h + 512 * 512, wc2_l + 512 * 512);
    biascat_layer_kernel<<<4, 256>>>(l2_b, g2_b, bcat2);
    tgemm(hh, hl, 512, nullptr, 0, wc2_h, wc2_l, 512, xslin, 1024,
          nullptr, nullptr, 0, NN, 1024, 1024, 16, bcat2, nullptr, 0);
    wproj_kernel<<<2, 256>>>(g2_ws, g2_wd, g2_as, g2_ad, wp2);
    coef_kernel<<<nAgg, 256>>>(hh, hl, wp2, asrc, adst);
    agg_kernel<<<nAgg, 256>>>(rowptr, csr, asrc, adst,
                              xslin, 1024, xslin + 512, 1024, hh, hl);

    // head
    TSPLIT(agg_w, HD, HID, 512, 128, wagg_h, wagg_l);
    tgemm(hh, hl, 512, nullptr, 0, wagg_h, wagg_l, 512, out_emb, HID,
          eh, el, 128, NN, HID, 128, 16, agg_b, nullptr, 1);

    TSPLIT(dr_w, HID, EMB, 128, 256, wdc_h,             wdc_l);
    TSPLIT(dp_w, HID, EMB, 128, 256, wdc_h + 256 * 128, wdc_l + 256 * 128);
    biascat_dec_kernel<<<2, 256>>>(dr_b, dp_b, bcatd);
    tgemm(eh, el, 128, nullptr, 0, wdc_h, wdc_l, 128, nullptr, 0,
          rdh, rdl, 512, NN, 512, 512, 4, bcatd, nullptr, 0);

    TSPLIT(rr_w, EMB, RNA, 256, 2048, wrr_h, wrr_l);
    tgemm(rdh, rdl, 512, nullptr, 0, wrr_h, wrr_l, 256, out_rna, RNA,
          nullptr, nullptr, 0, NN, RNA, 2048, 8, rr_b, nullptr, 0);
    TSPLIT(rp_w, EMB, PROT, 256, 128, wrp_h, wrp_l);
    tgemm(rdh + 256, rdl + 256, 512, nullptr, 0, wrp_h, wrp_l, 256, out_prot, PROT,
          nullptr, nullptr, 0, NN, PROT, 128, 8, rp_b, nullptr, 0);
}